// round 2
// baseline (speedup 1.0000x reference)
#include <cuda_runtime.h>
#include <math.h>
#include <stdint.h>

// ---------------- problem constants ----------------
#define T_STEPS 600
#define BATCH   64
#define HID     40
#define IN_F    257
#define NTOK    (BATCH * T_STEPS)   // 38400
#define G3H     120                 // 3*HID
#define KEXP    720                 // 80 silu + 80*8 spline bases
#define TWOH    80

// ---------------- scratch (static device memory; no allocations) ----------------
__device__ float g_giF[(size_t)T_STEPS * BATCH * G3H];   // layer-0 fwd input gates, (t,b,120)
__device__ float g_giB[(size_t)T_STEPS * BATCH * G3H];   // layer-0 bwd input gates, (t,b,120)
__device__ float g_hcat[(size_t)NTOK * TWOH];            // (b,t,80) concat fwd|bwd top-layer h
__device__ float g_feat[(size_t)NTOK * KEXP];            // expanded KAN features
__device__ float g_y1[(size_t)NTOK * TWOH];              // kan1 output
__device__ float g_WA[240 * IN_F];                       // packed [f0_Wih ; b0_Wih]
__device__ float g_bA[240];                              // packed [f0_bih ; b0_bih]
__device__ float g_Wp1[TWOH * KEXP];                     // packed kan1 weights
__device__ float g_Wp2[IN_F * KEXP];                     // packed kan2 weights

// ---------------- helpers ----------------
__device__ __forceinline__ float sigm_acc(float x) { return 1.0f / (1.0f + expf(-x)); }

// ---------------- weight packing ----------------
__global__ void pack_weights(const float* __restrict__ f0W, const float* __restrict__ b0W,
                             const float* __restrict__ f0b, const float* __restrict__ b0b,
                             const float* __restrict__ k1b, const float* __restrict__ k1s,
                             const float* __restrict__ k1c,
                             const float* __restrict__ k2b, const float* __restrict__ k2s,
                             const float* __restrict__ k2c)
{
    const int NWA  = 240 * IN_F;        // 61680
    const int NBA  = 240;
    const int NW1  = TWOH * KEXP;       // 57600
    const int NW2  = IN_F * KEXP;       // 185040
    int idx = blockIdx.x * blockDim.x + threadIdx.x;
    int total = NWA + NBA + NW1 + NW2;
    if (idx >= total) return;
    if (idx < NWA) {
        int r = idx / IN_F, c = idx % IN_F;
        g_WA[idx] = (r < G3H) ? f0W[r * IN_F + c] : b0W[(r - G3H) * IN_F + c];
        return;
    }
    idx -= NWA;
    if (idx < NBA) {
        g_bA[idx] = (idx < G3H) ? f0b[idx] : b0b[idx - G3H];
        return;
    }
    idx -= NBA;
    if (idx < NW1) {
        int o = idx / KEXP, k = idx % KEXP;
        if (k < TWOH) g_Wp1[idx] = k1b[o * TWOH + k];
        else {
            int e = k - TWOH, i = e >> 3, g = e & 7;
            g_Wp1[idx] = k1s[(o * TWOH + i) * 8 + g] * k1c[o * TWOH + i];
        }
        return;
    }
    idx -= NW1;
    {
        int o = idx / KEXP, k = idx % KEXP;
        if (k < TWOH) g_Wp2[idx] = k2b[o * TWOH + k];
        else {
            int e = k - TWOH, i = e >> 3, g = e & 7;
            g_Wp2[idx] = k2s[(o * TWOH + i) * 8 + g] * k2c[o * TWOH + i];
        }
    }
}

// ---------------- generic NT GEMM: C[n,m] = sum_k A[n,k]*B[m,k] (+bias, +epilogue) ----------------
// EPI 0: plain   EPI 1: scatter to g_giF/g_giB (gates)   EPI 2: 1.2*sigmoid(slope*v)
#define BMg 64
#define BNg 64
#define BKg 16

template <int EPI>
__global__ __launch_bounds__(256) void gemm_nt(
    const float* __restrict__ A, const float* __restrict__ B,
    const float* __restrict__ bias, float* __restrict__ C, float* __restrict__ C2,
    int N, int M, int K, const float* __restrict__ slope)
{
    __shared__ __align__(16) float As[BKg][BMg];
    __shared__ __align__(16) float Bs[BKg][BNg];

    const int tid  = threadIdx.x;
    const int rowT = blockIdx.x * BMg;
    const int colT = blockIdx.y * BNg;
    const int ty = tid >> 4;        // 0..15
    const int tx = tid & 15;        // 0..15
    const int lr = tid >> 2;        // 0..63
    const int lk = (tid & 3) * 4;   // 0,4,8,12

    float acc[4][4];
#pragma unroll
    for (int i = 0; i < 4; i++)
#pragma unroll
        for (int j = 0; j < 4; j++) acc[i][j] = 0.0f;

    for (int k0 = 0; k0 < K; k0 += BKg) {
#pragma unroll
        for (int i = 0; i < 4; i++) {
            int k = k0 + lk + i;
            As[lk + i][lr] = (k < K) ? A[(size_t)(rowT + lr) * K + k] : 0.0f;
            Bs[lk + i][lr] = (k < K && (colT + lr) < M) ? B[(size_t)(colT + lr) * K + k] : 0.0f;
        }
        __syncthreads();
#pragma unroll
        for (int k = 0; k < BKg; k++) {
            float4 a  = *(const float4*)&As[k][ty * 4];
            float4 bv = *(const float4*)&Bs[k][tx * 4];
            float av[4] = {a.x, a.y, a.z, a.w};
            float bb[4] = {bv.x, bv.y, bv.z, bv.w};
#pragma unroll
            for (int i = 0; i < 4; i++)
#pragma unroll
                for (int j = 0; j < 4; j++) acc[i][j] += av[i] * bb[j];
        }
        __syncthreads();
    }

#pragma unroll
    for (int i = 0; i < 4; i++) {
        int row = rowT + ty * 4 + i;
        if (row >= N) continue;
#pragma unroll
        for (int j = 0; j < 4; j++) {
            int col = colT + tx * 4 + j;
            if (col >= M) continue;
            float v = acc[i][j] + (bias ? bias[col] : 0.0f);
            if (EPI == 0) {
                C[(size_t)row * M + col] = v;
            } else if (EPI == 1) {
                int bb_ = row / T_STEPS, tt = row % T_STEPS;
                size_t o = ((size_t)tt * BATCH + bb_) * G3H;
                if (col < G3H) C[o + col] = v;
                else           C2[o + col - G3H] = v;
            } else {
                C[(size_t)row * M + col] = 1.2f / (1.0f + expf(-slope[col] * v));
            }
        }
    }
}

// ---------------- GRU scan: grid (64, 2) = (batch, dir), 256 threads ----------------
__global__ __launch_bounds__(256) void gru_scan(
    const float* __restrict__ WhhF0, const float* __restrict__ bhhF0,
    const float* __restrict__ WihF1, const float* __restrict__ WhhF1,
    const float* __restrict__ bihF1, const float* __restrict__ bhhF1,
    const float* __restrict__ WhhB0, const float* __restrict__ bhhB0,
    const float* __restrict__ WihB1, const float* __restrict__ WhhB1,
    const float* __restrict__ bihB1, const float* __restrict__ bhhB1)
{
    const int b   = blockIdx.x;
    const int dir = blockIdx.y;
    const float* Whh0 = dir ? WhhB0 : WhhF0;
    const float* bhh0 = dir ? bhhB0 : bhhF0;
    const float* W1ih = dir ? WihB1 : WihF1;
    const float* W1hh = dir ? WhhB1 : WhhF1;
    const float* b1ih = dir ? bihB1 : bihF1;
    const float* b1hh = dir ? bhhB1 : bhhF1;
    const float* gi   = dir ? g_giB : g_giF;
    float* out = g_hcat + (size_t)b * T_STEPS * TWOH + dir * HID;

    __shared__ __align__(16) float s_h0[HID];
    __shared__ __align__(16) float s_h1[HID];
    __shared__ float s_gh0[G3H], s_gh1[G3H], s_gi0[G3H], s_gi1[G3H];

    const int tid = threadIdx.x;
    if (tid < HID) { s_h0[tid] = 0.0f; s_h1[tid] = 0.0f; }

    float w0[HID];
    float wa[HID], wb[HID];
    float bias0 = 0.0f, biasA = 0.0f, biasB = 0.0f;
    if (tid < G3H) {
#pragma unroll
        for (int k = 0; k < HID; k++) w0[k] = Whh0[tid * HID + k];
        bias0 = bhh0[tid];
    } else if (tid >= 128 && tid < 128 + G3H) {
        int j = tid - 128;
#pragma unroll
        for (int k = 0; k < HID; k++) { wa[k] = W1hh[j * HID + k]; wb[k] = W1ih[j * HID + k]; }
        biasA = b1hh[j];
        biasB = b1ih[j];
    }
    __syncthreads();

    for (int t = 0; t < T_STEPS; t++) {
        // P1: layer0 recurrent gates + layer1 recurrent gates (independent), prefetch gi0
        if (tid < G3H) {
            int grow = dir ? (T_STEPS - 1 - t) : t;
            s_gi0[tid] = gi[((size_t)grow * BATCH + b) * G3H + tid];
            float acc = bias0;
            const float4* h4 = (const float4*)s_h0;
#pragma unroll
            for (int k = 0; k < HID / 4; k++) {
                float4 h = h4[k];
                acc += h.x * w0[4 * k] + h.y * w0[4 * k + 1] + h.z * w0[4 * k + 2] + h.w * w0[4 * k + 3];
            }
            s_gh0[tid] = acc;
        } else if (tid >= 128 && tid < 128 + G3H) {
            int j = tid - 128;
            float acc = biasA;
            const float4* h4 = (const float4*)s_h1;
#pragma unroll
            for (int k = 0; k < HID / 4; k++) {
                float4 h = h4[k];
                acc += h.x * wa[4 * k] + h.y * wa[4 * k + 1] + h.z * wa[4 * k + 2] + h.w * wa[4 * k + 3];
            }
            s_gh1[j] = acc;
        }
        __syncthreads();
        // P2: h0 update
        if (tid < HID) {
            float r = sigm_acc(s_gi0[tid] + s_gh0[tid]);
            float z = sigm_acc(s_gi0[HID + tid] + s_gh0[HID + tid]);
            float n = tanhf(s_gi0[2 * HID + tid] + r * s_gh0[2 * HID + tid]);
            s_h0[tid] = (1.0f - z) * n + z * s_h0[tid];
        }
        __syncthreads();
        // P3: layer1 input gates from fresh h0
        if (tid >= 128 && tid < 128 + G3H) {
            int j = tid - 128;
            float acc = biasB;
            const float4* h4 = (const float4*)s_h0;
#pragma unroll
            for (int k = 0; k < HID / 4; k++) {
                float4 h = h4[k];
                acc += h.x * wb[4 * k] + h.y * wb[4 * k + 1] + h.z * wb[4 * k + 2] + h.w * wb[4 * k + 3];
            }
            s_gi1[j] = acc;
        }
        __syncthreads();
        // P4: h1 update + store
        if (tid < HID) {
            float r = sigm_acc(s_gi1[tid] + s_gh1[tid]);
            float z = sigm_acc(s_gi1[HID + tid] + s_gh1[HID + tid]);
            float n = tanhf(s_gi1[2 * HID + tid] + r * s_gh1[2 * HID + tid]);
            float h = (1.0f - z) * n + z * s_h1[tid];
            s_h1[tid] = h;
            out[(size_t)t * TWOH + tid] = h;
        }
        __syncthreads();
    }
}

// ---------------- KAN feature expansion: silu + cubic B-spline bases (uniform grid) ----------------
__device__ __forceinline__ float gridv(int j) { return 0.4f * (float)(j - 3) - 1.0f; }

__global__ void expand_feat(const float* __restrict__ X, int total)
{
    int idx = blockIdx.x * blockDim.x + threadIdx.x;
    if (idx >= total) return;
    int n = idx / TWOH;
    int i = idx % TWOH;
    float x = X[idx];

    // silu
    g_feat[(size_t)n * KEXP + i] = x / (1.0f + expf(-x));

    // order-0 bases on 11 intervals
    float bset[11];
#pragma unroll
    for (int j = 0; j < 11; j++)
        bset[j] = (x >= gridv(j) && x < gridv(j + 1)) ? 1.0f : 0.0f;
    // k = 1 (denom 0.4)
#pragma unroll
    for (int j = 0; j < 10; j++)
        bset[j] = (x - gridv(j)) * 2.5f * bset[j] + (gridv(j + 2) - x) * 2.5f * bset[j + 1];
    // k = 2 (denom 0.8)
#pragma unroll
    for (int j = 0; j < 9; j++)
        bset[j] = (x - gridv(j)) * 1.25f * bset[j] + (gridv(j + 3) - x) * 1.25f * bset[j + 1];
    // k = 3 (denom 1.2)
#pragma unroll
    for (int j = 0; j < 8; j++)
        bset[j] = (x - gridv(j)) * (1.0f / 1.2f) * bset[j] + (gridv(j + 4) - x) * (1.0f / 1.2f) * bset[j + 1];

    float4* o = (float4*)&g_feat[(size_t)n * KEXP + TWOH + i * 8];
    o[0] = make_float4(bset[0], bset[1], bset[2], bset[3]);
    o[1] = make_float4(bset[4], bset[5], bset[6], bset[7]);
}

// ---------------- launch ----------------
extern "C" void kernel_launch(void* const* d_in, const int* in_sizes, int n_in,
                              void* d_out, int out_size)
{
    const float* x     = (const float*)d_in[0];
    // d_in[1] = lengths (unused, matches reference)
    const float* f0Wih = (const float*)d_in[2];
    const float* f0Whh = (const float*)d_in[3];
    const float* f0bih = (const float*)d_in[4];
    const float* f0bhh = (const float*)d_in[5];
    const float* f1Wih = (const float*)d_in[6];
    const float* f1Whh = (const float*)d_in[7];
    const float* f1bih = (const float*)d_in[8];
    const float* f1bhh = (const float*)d_in[9];
    const float* b0Wih = (const float*)d_in[10];
    const float* b0Whh = (const float*)d_in[11];
    const float* b0bih = (const float*)d_in[12];
    const float* b0bhh = (const float*)d_in[13];
    const float* b1Wih = (const float*)d_in[14];
    const float* b1Whh = (const float*)d_in[15];
    const float* b1bih = (const float*)d_in[16];
    const float* b1bhh = (const float*)d_in[17];
    const float* k1b   = (const float*)d_in[18];
    const float* k1s   = (const float*)d_in[19];
    const float* k1c   = (const float*)d_in[20];
    const float* k2b   = (const float*)d_in[21];
    const float* k2s   = (const float*)d_in[22];
    const float* k2c   = (const float*)d_in[23];
    const float* slope = (const float*)d_in[24];
    float* out = (float*)d_out;

    float *p_giF, *p_giB, *p_hcat, *p_feat, *p_y1, *p_WA, *p_bA, *p_Wp1, *p_Wp2;
    cudaGetSymbolAddress((void**)&p_giF, g_giF);
    cudaGetSymbolAddress((void**)&p_giB, g_giB);
    cudaGetSymbolAddress((void**)&p_hcat, g_hcat);
    cudaGetSymbolAddress((void**)&p_feat, g_feat);
    cudaGetSymbolAddress((void**)&p_y1, g_y1);
    cudaGetSymbolAddress((void**)&p_WA, g_WA);
    cudaGetSymbolAddress((void**)&p_bA, g_bA);
    cudaGetSymbolAddress((void**)&p_Wp1, g_Wp1);
    cudaGetSymbolAddress((void**)&p_Wp2, g_Wp2);

    // 1. pack weights
    {
        int total = 240 * IN_F + 240 + TWOH * KEXP + IN_F * KEXP;
        pack_weights<<<(total + 255) / 256, 256>>>(f0Wih, b0Wih, f0bih, b0bih,
                                                   k1b, k1s, k1c, k2b, k2s, k2c);
    }
    // 2. layer-0 input gates for both directions: (38400 x 257) @ (240 x 257)^T
    {
        dim3 grid(NTOK / BMg, (240 + BNg - 1) / BNg);
        gemm_nt<1><<<grid, 256>>>(x, p_WA, p_bA, p_giF, p_giB, NTOK, 240, IN_F, nullptr);
    }
    // 3. bidirectional 2-layer GRU scan
    {
        dim3 grid(BATCH, 2);
        gru_scan<<<grid, 256>>>(f0Whh, f0bhh, f1Wih, f1Whh, f1bih, f1bhh,
                                b0Whh, b0bhh, b1Wih, b1Whh, b1bih, b1bhh);
    }
    // 4. KAN layer 1: expand + GEMM
    {
        int total = NTOK * TWOH;
        expand_feat<<<(total + 255) / 256, 256>>>(p_hcat, total);
        dim3 grid(NTOK / BMg, (TWOH + BNg - 1) / BNg);
        gemm_nt<0><<<grid, 256>>>(p_feat, p_Wp1, nullptr, p_y1, nullptr, NTOK, TWOH, KEXP, nullptr);
    }
    // 5. KAN layer 2: expand + GEMM + 1.2*sigmoid(slope*·)
    {
        int total = NTOK * TWOH;
        expand_feat<<<(total + 255) / 256, 256>>>(p_y1, total);
        dim3 grid(NTOK / BMg, (IN_F + BNg - 1) / BNg);
        gemm_nt<2><<<grid, 256>>>(p_feat, p_Wp2, nullptr, out, nullptr, NTOK, IN_F, KEXP, slope);
    }
    (void)in_sizes; (void)n_in; (void)out_size;
}

// round 3
// speedup vs baseline: 1.0016x; 1.0016x over previous
#include <cuda_runtime.h>
#include <math.h>
#include <stdint.h>

// ---------------- problem constants ----------------
#define T_STEPS 600
#define BATCH   64
#define HID     40
#define IN_F    257
#define NTOK    (BATCH * T_STEPS)   // 38400
#define G3H     120                 // 3*HID
#define KEXP    720                 // 80 silu + 80*8 spline bases
#define TWOH    80

// ---------------- scratch (static device memory; no allocations) ----------------
__device__ float g_giF[(size_t)T_STEPS * BATCH * G3H];   // layer-0 fwd input gates, (t,b,120)
__device__ float g_giB[(size_t)T_STEPS * BATCH * G3H];   // layer-0 bwd input gates, (t,b,120)
__device__ float g_hcat[(size_t)NTOK * TWOH];            // (b,t,80) concat fwd|bwd top-layer h
__device__ float g_feat[(size_t)NTOK * KEXP];            // expanded KAN features
__device__ float g_y1[(size_t)NTOK * TWOH];              // kan1 output
__device__ float g_WA[240 * IN_F];                       // packed [f0_Wih ; b0_Wih]
__device__ float g_bA[240];                              // packed [f0_bih ; b0_bih]
__device__ float g_Wp1[TWOH * KEXP];                     // packed kan1 weights
__device__ float g_Wp2[IN_F * KEXP];                     // packed kan2 weights

// ---------------- helpers ----------------
__device__ __forceinline__ float sigm_acc(float x) { return 1.0f / (1.0f + expf(-x)); }

// ---------------- weight packing ----------------
__global__ void pack_weights(const float* __restrict__ f0W, const float* __restrict__ b0W,
                             const float* __restrict__ f0b, const float* __restrict__ b0b,
                             const float* __restrict__ k1b, const float* __restrict__ k1s,
                             const float* __restrict__ k1c,
                             const float* __restrict__ k2b, const float* __restrict__ k2s,
                             const float* __restrict__ k2c)
{
    const int NWA  = 240 * IN_F;        // 61680
    const int NBA  = 240;
    const int NW1  = TWOH * KEXP;       // 57600
    const int NW2  = IN_F * KEXP;       // 185040
    int idx = blockIdx.x * blockDim.x + threadIdx.x;
    int total = NWA + NBA + NW1 + NW2;
    if (idx >= total) return;
    if (idx < NWA) {
        int r = idx / IN_F, c = idx % IN_F;
        g_WA[idx] = (r < G3H) ? f0W[r * IN_F + c] : b0W[(r - G3H) * IN_F + c];
        return;
    }
    idx -= NWA;
    if (idx < NBA) {
        g_bA[idx] = (idx < G3H) ? f0b[idx] : b0b[idx - G3H];
        return;
    }
    idx -= NBA;
    if (idx < NW1) {
        int o = idx / KEXP, k = idx % KEXP;
        if (k < TWOH) g_Wp1[idx] = k1b[o * TWOH + k];
        else {
            int e = k - TWOH, i = e >> 3, g = e & 7;
            g_Wp1[idx] = k1s[(o * TWOH + i) * 8 + g] * k1c[o * TWOH + i];
        }
        return;
    }
    idx -= NW1;
    {
        int o = idx / KEXP, k = idx % KEXP;
        if (k < TWOH) g_Wp2[idx] = k2b[o * TWOH + k];
        else {
            int e = k - TWOH, i = e >> 3, g = e & 7;
            g_Wp2[idx] = k2s[(o * TWOH + i) * 8 + g] * k2c[o * TWOH + i];
        }
    }
}

// ---------------- generic NT GEMM: C[n,m] = sum_k A[n,k]*B[m,k] (+bias, +epilogue) ----------------
// EPI 0: plain   EPI 1: scatter to g_giF/g_giB (gates)   EPI 2: 1.2*sigmoid(slope*v)
#define BMg 64
#define BNg 64
#define BKg 16

template <int EPI>
__global__ __launch_bounds__(256) void gemm_nt(
    const float* __restrict__ A, const float* __restrict__ B,
    const float* __restrict__ bias, float* __restrict__ C, float* __restrict__ C2,
    int N, int M, int K, const float* __restrict__ slope)
{
    __shared__ __align__(16) float As[BKg][BMg];
    __shared__ __align__(16) float Bs[BKg][BNg];

    const int tid  = threadIdx.x;
    const int rowT = blockIdx.x * BMg;
    const int colT = blockIdx.y * BNg;
    const int ty = tid >> 4;        // 0..15
    const int tx = tid & 15;        // 0..15
    const int lr = tid >> 2;        // 0..63
    const int lk = (tid & 3) * 4;   // 0,4,8,12

    float acc[4][4];
#pragma unroll
    for (int i = 0; i < 4; i++)
#pragma unroll
        for (int j = 0; j < 4; j++) acc[i][j] = 0.0f;

    for (int k0 = 0; k0 < K; k0 += BKg) {
#pragma unroll
        for (int i = 0; i < 4; i++) {
            int k = k0 + lk + i;
            As[lk + i][lr] = (k < K) ? A[(size_t)(rowT + lr) * K + k] : 0.0f;
            Bs[lk + i][lr] = (k < K && (colT + lr) < M) ? B[(size_t)(colT + lr) * K + k] : 0.0f;
        }
        __syncthreads();
#pragma unroll
        for (int k = 0; k < BKg; k++) {
            float4 a  = *(const float4*)&As[k][ty * 4];
            float4 bv = *(const float4*)&Bs[k][tx * 4];
            float av[4] = {a.x, a.y, a.z, a.w};
            float bb[4] = {bv.x, bv.y, bv.z, bv.w};
#pragma unroll
            for (int i = 0; i < 4; i++)
#pragma unroll
                for (int j = 0; j < 4; j++) acc[i][j] += av[i] * bb[j];
        }
        __syncthreads();
    }

#pragma unroll
    for (int i = 0; i < 4; i++) {
        int row = rowT + ty * 4 + i;
        if (row >= N) continue;
#pragma unroll
        for (int j = 0; j < 4; j++) {
            int col = colT + tx * 4 + j;
            if (col >= M) continue;
            float v = acc[i][j] + (bias ? bias[col] : 0.0f);
            if (EPI == 0) {
                C[(size_t)row * M + col] = v;
            } else if (EPI == 1) {
                int bb_ = row / T_STEPS, tt = row % T_STEPS;
                size_t o = ((size_t)tt * BATCH + bb_) * G3H;
                if (col < G3H) C[o + col] = v;
                else           C2[o + col - G3H] = v;
            } else {
                C[(size_t)row * M + col] = 1.2f / (1.0f + expf(-slope[col] * v));
            }
        }
    }
}

// ---------------- GRU scan: grid (64, 2) = (batch, dir), 256 threads ----------------
__global__ __launch_bounds__(256) void gru_scan(
    const float* __restrict__ WhhF0, const float* __restrict__ bhhF0,
    const float* __restrict__ WihF1, const float* __restrict__ WhhF1,
    const float* __restrict__ bihF1, const float* __restrict__ bhhF1,
    const float* __restrict__ WhhB0, const float* __restrict__ bhhB0,
    const float* __restrict__ WihB1, const float* __restrict__ WhhB1,
    const float* __restrict__ bihB1, const float* __restrict__ bhhB1)
{
    const int b   = blockIdx.x;
    const int dir = blockIdx.y;
    const float* Whh0 = dir ? WhhB0 : WhhF0;
    const float* bhh0 = dir ? bhhB0 : bhhF0;
    const float* W1ih = dir ? WihB1 : WihF1;
    const float* W1hh = dir ? WhhB1 : WhhF1;
    const float* b1ih = dir ? bihB1 : bihF1;
    const float* b1hh = dir ? bhhB1 : bhhF1;
    const float* gi   = dir ? g_giB : g_giF;
    float* out = g_hcat + (size_t)b * T_STEPS * TWOH + dir * HID;

    __shared__ __align__(16) float s_h0[HID];
    __shared__ __align__(16) float s_h1[HID];
    __shared__ float s_gh0[G3H], s_gh1[G3H], s_gi0[G3H], s_gi1[G3H];

    const int tid = threadIdx.x;
    if (tid < HID) { s_h0[tid] = 0.0f; s_h1[tid] = 0.0f; }

    float w0[HID];
    float wa[HID], wb[HID];
    float bias0 = 0.0f, biasA = 0.0f, biasB = 0.0f;
    if (tid < G3H) {
#pragma unroll
        for (int k = 0; k < HID; k++) w0[k] = Whh0[tid * HID + k];
        bias0 = bhh0[tid];
    } else if (tid >= 128 && tid < 128 + G3H) {
        int j = tid - 128;
#pragma unroll
        for (int k = 0; k < HID; k++) { wa[k] = W1hh[j * HID + k]; wb[k] = W1ih[j * HID + k]; }
        biasA = b1hh[j];
        biasB = b1ih[j];
    }
    __syncthreads();

    for (int t = 0; t < T_STEPS; t++) {
        // P1: layer0 recurrent gates + layer1 recurrent gates (independent), prefetch gi0
        if (tid < G3H) {
            int grow = dir ? (T_STEPS - 1 - t) : t;
            s_gi0[tid] = gi[((size_t)grow * BATCH + b) * G3H + tid];
            float acc = bias0;
            const float4* h4 = (const float4*)s_h0;
#pragma unroll
            for (int k = 0; k < HID / 4; k++) {
                float4 h = h4[k];
                acc += h.x * w0[4 * k] + h.y * w0[4 * k + 1] + h.z * w0[4 * k + 2] + h.w * w0[4 * k + 3];
            }
            s_gh0[tid] = acc;
        } else if (tid >= 128 && tid < 128 + G3H) {
            int j = tid - 128;
            float acc = biasA;
            const float4* h4 = (const float4*)s_h1;
#pragma unroll
            for (int k = 0; k < HID / 4; k++) {
                float4 h = h4[k];
                acc += h.x * wa[4 * k] + h.y * wa[4 * k + 1] + h.z * wa[4 * k + 2] + h.w * wa[4 * k + 3];
            }
            s_gh1[j] = acc;
        }
        __syncthreads();
        // P2: h0 update
        if (tid < HID) {
            float r = sigm_acc(s_gi0[tid] + s_gh0[tid]);
            float z = sigm_acc(s_gi0[HID + tid] + s_gh0[HID + tid]);
            float n = tanhf(s_gi0[2 * HID + tid] + r * s_gh0[2 * HID + tid]);
            s_h0[tid] = (1.0f - z) * n + z * s_h0[tid];
        }
        __syncthreads();
        // P3: layer1 input gates from fresh h0
        if (tid >= 128 && tid < 128 + G3H) {
            int j = tid - 128;
            float acc = biasB;
            const float4* h4 = (const float4*)s_h0;
#pragma unroll
            for (int k = 0; k < HID / 4; k++) {
                float4 h = h4[k];
                acc += h.x * wb[4 * k] + h.y * wb[4 * k + 1] + h.z * wb[4 * k + 2] + h.w * wb[4 * k + 3];
            }
            s_gi1[j] = acc;
        }
        __syncthreads();
        // P4: h1 update + store
        if (tid < HID) {
            float r = sigm_acc(s_gi1[tid] + s_gh1[tid]);
            float z = sigm_acc(s_gi1[HID + tid] + s_gh1[HID + tid]);
            float n = tanhf(s_gi1[2 * HID + tid] + r * s_gh1[2 * HID + tid]);
            float h = (1.0f - z) * n + z * s_h1[tid];
            s_h1[tid] = h;
            out[(size_t)t * TWOH + tid] = h;
        }
        __syncthreads();
    }
}

// ---------------- KAN feature expansion: silu + cubic B-spline bases (uniform grid) ----------------
__device__ __forceinline__ float gridv(int j) { return 0.4f * (float)(j - 3) - 1.0f; }

__global__ void expand_feat(const float* __restrict__ X, int total)
{
    int idx = blockIdx.x * blockDim.x + threadIdx.x;
    if (idx >= total) return;
    int n = idx / TWOH;
    int i = idx % TWOH;
    float x = X[idx];

    // silu
    g_feat[(size_t)n * KEXP + i] = x / (1.0f + expf(-x));

    // order-0 bases on 11 intervals
    float bset[11];
#pragma unroll
    for (int j = 0; j < 11; j++)
        bset[j] = (x >= gridv(j) && x < gridv(j + 1)) ? 1.0f : 0.0f;
    // k = 1 (denom 0.4)
#pragma unroll
    for (int j = 0; j < 10; j++)
        bset[j] = (x - gridv(j)) * 2.5f * bset[j] + (gridv(j + 2) - x) * 2.5f * bset[j + 1];
    // k = 2 (denom 0.8)
#pragma unroll
    for (int j = 0; j < 9; j++)
        bset[j] = (x - gridv(j)) * 1.25f * bset[j] + (gridv(j + 3) - x) * 1.25f * bset[j + 1];
    // k = 3 (denom 1.2)
#pragma unroll
    for (int j = 0; j < 8; j++)
        bset[j] = (x - gridv(j)) * (1.0f / 1.2f) * bset[j] + (gridv(j + 4) - x) * (1.0f / 1.2f) * bset[j + 1];

    float4* o = (float4*)&g_feat[(size_t)n * KEXP + TWOH + i * 8];
    o[0] = make_float4(bset[0], bset[1], bset[2], bset[3]);
    o[1] = make_float4(bset[4], bset[5], bset[6], bset[7]);
}

// ---------------- launch ----------------
extern "C" void kernel_launch(void* const* d_in, const int* in_sizes, int n_in,
                              void* d_out, int out_size)
{
    const float* x     = (const float*)d_in[0];
    // d_in[1] = lengths (unused, matches reference)
    const float* f0Wih = (const float*)d_in[2];
    const float* f0Whh = (const float*)d_in[3];
    const float* f0bih = (const float*)d_in[4];
    const float* f0bhh = (const float*)d_in[5];
    const float* f1Wih = (const float*)d_in[6];
    const float* f1Whh = (const float*)d_in[7];
    const float* f1bih = (const float*)d_in[8];
    const float* f1bhh = (const float*)d_in[9];
    const float* b0Wih = (const float*)d_in[10];
    const float* b0Whh = (const float*)d_in[11];
    const float* b0bih = (const float*)d_in[12];
    const float* b0bhh = (const float*)d_in[13];
    const float* b1Wih = (const float*)d_in[14];
    const float* b1Whh = (const float*)d_in[15];
    const float* b1bih = (const float*)d_in[16];
    const float* b1bhh = (const float*)d_in[17];
    const float* k1b   = (const float*)d_in[18];
    const float* k1s   = (const float*)d_in[19];
    const float* k1c   = (const float*)d_in[20];
    const float* k2b   = (const float*)d_in[21];
    const float* k2s   = (const float*)d_in[22];
    const float* k2c   = (const float*)d_in[23];
    const float* slope = (const float*)d_in[24];
    float* out = (float*)d_out;

    float *p_giF, *p_giB, *p_hcat, *p_feat, *p_y1, *p_WA, *p_bA, *p_Wp1, *p_Wp2;
    cudaGetSymbolAddress((void**)&p_giF, g_giF);
    cudaGetSymbolAddress((void**)&p_giB, g_giB);
    cudaGetSymbolAddress((void**)&p_hcat, g_hcat);
    cudaGetSymbolAddress((void**)&p_feat, g_feat);
    cudaGetSymbolAddress((void**)&p_y1, g_y1);
    cudaGetSymbolAddress((void**)&p_WA, g_WA);
    cudaGetSymbolAddress((void**)&p_bA, g_bA);
    cudaGetSymbolAddress((void**)&p_Wp1, g_Wp1);
    cudaGetSymbolAddress((void**)&p_Wp2, g_Wp2);

    // 1. pack weights
    {
        int total = 240 * IN_F + 240 + TWOH * KEXP + IN_F * KEXP;
        pack_weights<<<(total + 255) / 256, 256>>>(f0Wih, b0Wih, f0bih, b0bih,
                                                   k1b, k1s, k1c, k2b, k2s, k2c);
    }
    // 2. layer-0 input gates for both directions: (38400 x 257) @ (240 x 257)^T
    {
        dim3 grid(NTOK / BMg, (240 + BNg - 1) / BNg);
        gemm_nt<1><<<grid, 256>>>(x, p_WA, p_bA, p_giF, p_giB, NTOK, 240, IN_F, nullptr);
    }
    // 3. bidirectional 2-layer GRU scan
    {
        dim3 grid(BATCH, 2);
        gru_scan<<<grid, 256>>>(f0Whh, f0bhh, f1Wih, f1Whh, f1bih, f1bhh,
                                b0Whh, b0bhh, b1Wih, b1Whh, b1bih, b1bhh);
    }
    // 4. KAN layer 1: expand + GEMM
    {
        int total = NTOK * TWOH;
        expand_feat<<<(total + 255) / 256, 256>>>(p_hcat, total);
        dim3 grid(NTOK / BMg, (TWOH + BNg - 1) / BNg);
        gemm_nt<0><<<grid, 256>>>(p_feat, p_Wp1, nullptr, p_y1, nullptr, NTOK, TWOH, KEXP, nullptr);
    }
    // 5. KAN layer 2: expand + GEMM + 1.2*sigmoid(slope*·)
    {
        int total = NTOK * TWOH;
        expand_feat<<<(total + 255) / 256, 256>>>(p_y1, total);
        dim3 grid(NTOK / BMg, (IN_F + BNg - 1) / BNg);
        gemm_nt<2><<<grid, 256>>>(p_feat, p_Wp2, nullptr, out, nullptr, NTOK, IN_F, KEXP, slope);
    }
    (void)in_sizes; (void)n_in; (void)out_size;
}

// round 4
// speedup vs baseline: 1.2125x; 1.2106x over previous
#include <cuda_runtime.h>
#include <math.h>
#include <stdint.h>

// ---------------- problem constants ----------------
#define T_STEPS 600
#define BATCH   64
#define HID     40
#define IN_F    257
#define NTOK    (BATCH * T_STEPS)   // 38400
#define G3H     120                 // 3*HID
#define KEXP    720                 // 80 silu + 80*8 spline bases
#define TWOH    80

// ---------------- scratch (static device memory; no allocations) ----------------
__device__ float g_giF[(size_t)T_STEPS * BATCH * G3H];   // layer-0 fwd input gates, (t,b,120)
__device__ float g_giB[(size_t)T_STEPS * BATCH * G3H];   // layer-0 bwd input gates, (t,b,120)
__device__ float g_hcat[(size_t)NTOK * TWOH];            // (b,t,80) concat fwd|bwd top-layer h
__device__ float g_feat[(size_t)NTOK * KEXP];            // expanded KAN features
__device__ float g_y1[(size_t)NTOK * TWOH];              // kan1 output
__device__ float g_WA[240 * IN_F];                       // packed [f0_Wih ; b0_Wih]
__device__ float g_bA[240];                              // packed [f0_bih ; b0_bih]
__device__ float g_Wp1[TWOH * KEXP];                     // packed kan1 weights
__device__ float g_Wp2[IN_F * KEXP];                     // packed kan2 weights

// ---------------- helpers ----------------
__device__ __forceinline__ float sigm_fast(float x) { return 1.0f / (1.0f + __expf(-x)); }
__device__ __forceinline__ float tanh_fast(float x) {
    float ax = fabsf(x);
    float e = __expf(-2.0f * ax);
    float t = (1.0f - e) / (1.0f + e);
    return copysignf(t, x);
}

// ---------------- weight packing ----------------
__global__ void pack_weights(const float* __restrict__ f0W, const float* __restrict__ b0W,
                             const float* __restrict__ f0b, const float* __restrict__ b0b,
                             const float* __restrict__ k1b, const float* __restrict__ k1s,
                             const float* __restrict__ k1c,
                             const float* __restrict__ k2b, const float* __restrict__ k2s,
                             const float* __restrict__ k2c)
{
    const int NWA  = 240 * IN_F;        // 61680
    const int NBA  = 240;
    const int NW1  = TWOH * KEXP;       // 57600
    const int NW2  = IN_F * KEXP;       // 185040
    int idx = blockIdx.x * blockDim.x + threadIdx.x;
    int total = NWA + NBA + NW1 + NW2;
    if (idx >= total) return;
    if (idx < NWA) {
        int r = idx / IN_F, c = idx % IN_F;
        g_WA[idx] = (r < G3H) ? f0W[r * IN_F + c] : b0W[(r - G3H) * IN_F + c];
        return;
    }
    idx -= NWA;
    if (idx < NBA) {
        g_bA[idx] = (idx < G3H) ? f0b[idx] : b0b[idx - G3H];
        return;
    }
    idx -= NBA;
    if (idx < NW1) {
        int o = idx / KEXP, k = idx % KEXP;
        if (k < TWOH) g_Wp1[idx] = k1b[o * TWOH + k];
        else {
            int e = k - TWOH, i = e >> 3, g = e & 7;
            g_Wp1[idx] = k1s[(o * TWOH + i) * 8 + g] * k1c[o * TWOH + i];
        }
        return;
    }
    idx -= NW1;
    {
        int o = idx / KEXP, k = idx % KEXP;
        if (k < TWOH) g_Wp2[idx] = k2b[o * TWOH + k];
        else {
            int e = k - TWOH, i = e >> 3, g = e & 7;
            g_Wp2[idx] = k2s[(o * TWOH + i) * 8 + g] * k2c[o * TWOH + i];
        }
    }
}

// ---------------- generic NT GEMM: C[n,m] = sum_k A[n,k]*B[m,k] (+bias, +epilogue) ----------------
// EPI 0: plain   EPI 1: scatter to g_giF/g_giB (gates)   EPI 2: 1.2*sigmoid(slope*v)
#define BMg 64
#define BNg 64
#define BKg 16

template <int EPI>
__global__ __launch_bounds__(256) void gemm_nt(
    const float* __restrict__ A, const float* __restrict__ B,
    const float* __restrict__ bias, float* __restrict__ C, float* __restrict__ C2,
    int N, int M, int K, const float* __restrict__ slope)
{
    __shared__ __align__(16) float As[BKg][BMg];
    __shared__ __align__(16) float Bs[BKg][BNg];

    const int tid  = threadIdx.x;
    const int rowT = blockIdx.x * BMg;
    const int colT = blockIdx.y * BNg;
    const int ty = tid >> 4;        // 0..15
    const int tx = tid & 15;        // 0..15
    const int lr = tid >> 2;        // 0..63
    const int lk = (tid & 3) * 4;   // 0,4,8,12

    float acc[4][4];
#pragma unroll
    for (int i = 0; i < 4; i++)
#pragma unroll
        for (int j = 0; j < 4; j++) acc[i][j] = 0.0f;

    for (int k0 = 0; k0 < K; k0 += BKg) {
#pragma unroll
        for (int i = 0; i < 4; i++) {
            int k = k0 + lk + i;
            As[lk + i][lr] = (k < K) ? A[(size_t)(rowT + lr) * K + k] : 0.0f;
            Bs[lk + i][lr] = (k < K && (colT + lr) < M) ? B[(size_t)(colT + lr) * K + k] : 0.0f;
        }
        __syncthreads();
#pragma unroll
        for (int k = 0; k < BKg; k++) {
            float4 a  = *(const float4*)&As[k][ty * 4];
            float4 bv = *(const float4*)&Bs[k][tx * 4];
            float av[4] = {a.x, a.y, a.z, a.w};
            float bb[4] = {bv.x, bv.y, bv.z, bv.w};
#pragma unroll
            for (int i = 0; i < 4; i++)
#pragma unroll
                for (int j = 0; j < 4; j++) acc[i][j] += av[i] * bb[j];
        }
        __syncthreads();
    }

#pragma unroll
    for (int i = 0; i < 4; i++) {
        int row = rowT + ty * 4 + i;
        if (row >= N) continue;
#pragma unroll
        for (int j = 0; j < 4; j++) {
            int col = colT + tx * 4 + j;
            if (col >= M) continue;
            float v = acc[i][j] + (bias ? bias[col] : 0.0f);
            if (EPI == 0) {
                C[(size_t)row * M + col] = v;
            } else if (EPI == 1) {
                int bb_ = row / T_STEPS, tt = row % T_STEPS;
                size_t o = ((size_t)tt * BATCH + bb_) * G3H;
                if (col < G3H) C[o + col] = v;
                else           C2[o + col - G3H] = v;
            } else {
                C[(size_t)row * M + col] = 1.2f / (1.0f + expf(-slope[col] * v));
            }
        }
    }
}

// ---------------- GRU scan v2: 1 barrier/step, pipelined layers ----------------
// grid (64, 2) = (batch, dir), 320 threads.
// Threads 0..159   = group A (layer 0): 40 units x 4 lanes
// Threads 160..319 = group B (layer 1): 40 units x 4 lanes
// Iteration s: A computes h0(s+1) from h0(s) + gi0(s); B computes h1(s) from
// h0(s), h1(s-1) and writes out[s-1]. Single __syncthreads per iteration.
__global__ __launch_bounds__(320) void gru_scan2(
    const float* __restrict__ WhhF0, const float* __restrict__ bhhF0,
    const float* __restrict__ WihF1, const float* __restrict__ WhhF1,
    const float* __restrict__ bihF1, const float* __restrict__ bhhF1,
    const float* __restrict__ WhhB0, const float* __restrict__ bhhB0,
    const float* __restrict__ WihB1, const float* __restrict__ WhhB1,
    const float* __restrict__ bihB1, const float* __restrict__ bhhB1)
{
    const int b   = blockIdx.x;
    const int dir = blockIdx.y;
    const float* Whh0 = dir ? WhhB0 : WhhF0;
    const float* bhh0 = dir ? bhhB0 : bhhF0;
    const float* W1ih = dir ? WihB1 : WihF1;
    const float* W1hh = dir ? WhhB1 : WhhF1;
    const float* b1ih = dir ? bihB1 : bihF1;
    const float* b1hh = dir ? bhhB1 : bhhF1;
    const float* gi   = dir ? g_giB : g_giF;
    float* out = g_hcat + (size_t)b * T_STEPS * TWOH + dir * HID;

    __shared__ float s_h0[2][HID];
    __shared__ float s_h1[2][HID];

    const int tid = threadIdx.x;
    const bool isA = tid < 160;
    const int lane = isA ? tid : tid - 160;
    const int unit = lane >> 2;
    const int q    = lane & 3;
    const int k0   = q * 10;

    // per-lane weight registers
    float wA[3][10];           // A: Whh0 rows {unit, 40+unit, 80+unit}, cols k0..k0+9
    float wI[3][10], wH[3][10];// B: W1ih / W1hh rows, same scheme
    float brz0 = 0.f, brz1 = 0.f, bn0 = 0.f;               // A biases (bhh r,z,n)
    float bR = 0.f, bZ = 0.f, bIN = 0.f, bHN = 0.f;        // B combined biases
    if (isA) {
#pragma unroll
        for (int g = 0; g < 3; g++)
#pragma unroll
            for (int k = 0; k < 10; k++)
                wA[g][k] = Whh0[(g * HID + unit) * HID + k0 + k];
        brz0 = bhh0[unit];
        brz1 = bhh0[HID + unit];
        bn0  = bhh0[2 * HID + unit];
    } else {
#pragma unroll
        for (int g = 0; g < 3; g++)
#pragma unroll
            for (int k = 0; k < 10; k++) {
                wI[g][k] = W1ih[(g * HID + unit) * HID + k0 + k];
                wH[g][k] = W1hh[(g * HID + unit) * HID + k0 + k];
            }
        bR  = b1ih[unit]           + b1hh[unit];
        bZ  = b1ih[HID + unit]     + b1hh[HID + unit];
        bIN = b1ih[2 * HID + unit];
        bHN = b1hh[2 * HID + unit];
    }

    if (tid < HID) { s_h0[0][tid] = 0.0f; s_h0[1][tid] = 0.0f;
                     s_h1[0][tid] = 0.0f; s_h1[1][tid] = 0.0f; }

    // prefetch gi0 for s = 0
    float gc0 = 0.f, gc1 = 0.f, gc2 = 0.f;
    if (isA) {
        int grow = dir ? (T_STEPS - 1) : 0;
        const float* gp = gi + ((size_t)grow * BATCH + b) * G3H;
        gc0 = gp[unit]; gc1 = gp[HID + unit]; gc2 = gp[2 * HID + unit];
    }
    __syncthreads();

    for (int s = 0; s <= T_STEPS; s++) {
        const int cur = s & 1, nxt = (s & 1) ^ 1;
        float gn0 = 0.f, gn1 = 0.f, gn2 = 0.f;

        if (isA) {
            // prefetch gi0 for s+1 (latency hidden behind compute + barrier)
            if (s + 1 < T_STEPS) {
                int grow = dir ? (T_STEPS - 2 - s) : (s + 1);
                const float* gp = gi + ((size_t)grow * BATCH + b) * G3H;
                gn0 = gp[unit]; gn1 = gp[HID + unit]; gn2 = gp[2 * HID + unit];
            }
            if (s < T_STEPS) {
                const float* h0c = s_h0[cur];
                float hk[10];
#pragma unroll
                for (int k = 0; k < 10; k++) hk[k] = h0c[k0 + k];
                float p0 = 0.f, p1 = 0.f, p2 = 0.f;
#pragma unroll
                for (int k = 0; k < 10; k++) {
                    p0 = fmaf(wA[0][k], hk[k], p0);
                    p1 = fmaf(wA[1][k], hk[k], p1);
                    p2 = fmaf(wA[2][k], hk[k], p2);
                }
                p0 += __shfl_xor_sync(0xffffffffu, p0, 1);
                p0 += __shfl_xor_sync(0xffffffffu, p0, 2);
                p1 += __shfl_xor_sync(0xffffffffu, p1, 1);
                p1 += __shfl_xor_sync(0xffffffffu, p1, 2);
                p2 += __shfl_xor_sync(0xffffffffu, p2, 1);
                p2 += __shfl_xor_sync(0xffffffffu, p2, 2);
                float r = sigm_fast(gc0 + p0 + brz0);
                float z = sigm_fast(gc1 + p1 + brz1);
                float n = tanh_fast(gc2 + r * (p2 + bn0));
                float hnew = (1.0f - z) * n + z * h0c[unit];
                if (q == 0) s_h0[nxt][unit] = hnew;
            }
        } else {
            if (s >= 1) {
                const float* h0c = s_h0[cur];   // h0(s)
                const float* h1c = s_h1[cur];   // h1(s-1)
                float a[10], hh[10];
#pragma unroll
                for (int k = 0; k < 10; k++) { a[k] = h0c[k0 + k]; hh[k] = h1c[k0 + k]; }
                float pr = 0.f, pz = 0.f, pin = 0.f, phn = 0.f;
#pragma unroll
                for (int k = 0; k < 10; k++) {
                    pr  = fmaf(wI[0][k], a[k], pr);
                    pz  = fmaf(wI[1][k], a[k], pz);
                    pin = fmaf(wI[2][k], a[k], pin);
                    phn = fmaf(wH[2][k], hh[k], phn);
                }
#pragma unroll
                for (int k = 0; k < 10; k++) {
                    pr = fmaf(wH[0][k], hh[k], pr);
                    pz = fmaf(wH[1][k], hh[k], pz);
                }
                pr  += __shfl_xor_sync(0xffffffffu, pr, 1);
                pr  += __shfl_xor_sync(0xffffffffu, pr, 2);
                pz  += __shfl_xor_sync(0xffffffffu, pz, 1);
                pz  += __shfl_xor_sync(0xffffffffu, pz, 2);
                pin += __shfl_xor_sync(0xffffffffu, pin, 1);
                pin += __shfl_xor_sync(0xffffffffu, pin, 2);
                phn += __shfl_xor_sync(0xffffffffu, phn, 1);
                phn += __shfl_xor_sync(0xffffffffu, phn, 2);
                float r = sigm_fast(pr + bR);
                float z = sigm_fast(pz + bZ);
                float n = tanh_fast(pin + bIN + r * (phn + bHN));
                float h = (1.0f - z) * n + z * h1c[unit];
                if (q == 0) {
                    s_h1[nxt][unit] = h;
                    out[(size_t)(s - 1) * TWOH + unit] = h;
                }
            }
        }
        __syncthreads();
        gc0 = gn0; gc1 = gn1; gc2 = gn2;
    }
}

// ---------------- KAN feature expansion: silu + cubic B-spline bases (uniform grid) ----------------
__device__ __forceinline__ float gridv(int j) { return 0.4f * (float)(j - 3) - 1.0f; }

__global__ void expand_feat(const float* __restrict__ X, int total)
{
    int idx = blockIdx.x * blockDim.x + threadIdx.x;
    if (idx >= total) return;
    int n = idx / TWOH;
    int i = idx % TWOH;
    float x = X[idx];

    // silu (keep accurate expf here: feeds long GEMM accumulations)
    g_feat[(size_t)n * KEXP + i] = x / (1.0f + expf(-x));

    // order-0 bases on 11 intervals
    float bset[11];
#pragma unroll
    for (int j = 0; j < 11; j++)
        bset[j] = (x >= gridv(j) && x < gridv(j + 1)) ? 1.0f : 0.0f;
    // k = 1 (denom 0.4)
#pragma unroll
    for (int j = 0; j < 10; j++)
        bset[j] = (x - gridv(j)) * 2.5f * bset[j] + (gridv(j + 2) - x) * 2.5f * bset[j + 1];
    // k = 2 (denom 0.8)
#pragma unroll
    for (int j = 0; j < 9; j++)
        bset[j] = (x - gridv(j)) * 1.25f * bset[j] + (gridv(j + 3) - x) * 1.25f * bset[j + 1];
    // k = 3 (denom 1.2)
#pragma unroll
    for (int j = 0; j < 8; j++)
        bset[j] = (x - gridv(j)) * (1.0f / 1.2f) * bset[j] + (gridv(j + 4) - x) * (1.0f / 1.2f) * bset[j + 1];

    float4* o = (float4*)&g_feat[(size_t)n * KEXP + TWOH + i * 8];
    o[0] = make_float4(bset[0], bset[1], bset[2], bset[3]);
    o[1] = make_float4(bset[4], bset[5], bset[6], bset[7]);
}

// ---------------- launch ----------------
extern "C" void kernel_launch(void* const* d_in, const int* in_sizes, int n_in,
                              void* d_out, int out_size)
{
    const float* x     = (const float*)d_in[0];
    // d_in[1] = lengths (unused, matches reference)
    const float* f0Wih = (const float*)d_in[2];
    const float* f0Whh = (const float*)d_in[3];
    const float* f0bih = (const float*)d_in[4];
    const float* f0bhh = (const float*)d_in[5];
    const float* f1Wih = (const float*)d_in[6];
    const float* f1Whh = (const float*)d_in[7];
    const float* f1bih = (const float*)d_in[8];
    const float* f1bhh = (const float*)d_in[9];
    const float* b0Wih = (const float*)d_in[10];
    const float* b0Whh = (const float*)d_in[11];
    const float* b0bih = (const float*)d_in[12];
    const float* b0bhh = (const float*)d_in[13];
    const float* b1Wih = (const float*)d_in[14];
    const float* b1Whh = (const float*)d_in[15];
    const float* b1bih = (const float*)d_in[16];
    const float* b1bhh = (const float*)d_in[17];
    const float* k1b   = (const float*)d_in[18];
    const float* k1s   = (const float*)d_in[19];
    const float* k1c   = (const float*)d_in[20];
    const float* k2b   = (const float*)d_in[21];
    const float* k2s   = (const float*)d_in[22];
    const float* k2c   = (const float*)d_in[23];
    const float* slope = (const float*)d_in[24];
    float* out = (float*)d_out;

    float *p_giF, *p_giB, *p_hcat, *p_feat, *p_y1, *p_WA, *p_bA, *p_Wp1, *p_Wp2;
    cudaGetSymbolAddress((void**)&p_giF, g_giF);
    cudaGetSymbolAddress((void**)&p_giB, g_giB);
    cudaGetSymbolAddress((void**)&p_hcat, g_hcat);
    cudaGetSymbolAddress((void**)&p_feat, g_feat);
    cudaGetSymbolAddress((void**)&p_y1, g_y1);
    cudaGetSymbolAddress((void**)&p_WA, g_WA);
    cudaGetSymbolAddress((void**)&p_bA, g_bA);
    cudaGetSymbolAddress((void**)&p_Wp1, g_Wp1);
    cudaGetSymbolAddress((void**)&p_Wp2, g_Wp2);

    // 1. pack weights
    {
        int total = 240 * IN_F + 240 + TWOH * KEXP + IN_F * KEXP;
        pack_weights<<<(total + 255) / 256, 256>>>(f0Wih, b0Wih, f0bih, b0bih,
                                                   k1b, k1s, k1c, k2b, k2s, k2c);
    }
    // 2. layer-0 input gates for both directions: (38400 x 257) @ (240 x 257)^T
    {
        dim3 grid(NTOK / BMg, (240 + BNg - 1) / BNg);
        gemm_nt<1><<<grid, 256>>>(x, p_WA, p_bA, p_giF, p_giB, NTOK, 240, IN_F, nullptr);
    }
    // 3. bidirectional 2-layer GRU scan (pipelined, 1 barrier/step)
    {
        dim3 grid(BATCH, 2);
        gru_scan2<<<grid, 320>>>(f0Whh, f0bhh, f1Wih, f1Whh, f1bih, f1bhh,
                                 b0Whh, b0bhh, b1Wih, b1Whh, b1bih, b1bhh);
    }
    // 4. KAN layer 1: expand + GEMM
    {
        int total = NTOK * TWOH;
        expand_feat<<<(total + 255) / 256, 256>>>(p_hcat, total);
        dim3 grid(NTOK / BMg, (TWOH + BNg - 1) / BNg);
        gemm_nt<0><<<grid, 256>>>(p_feat, p_Wp1, nullptr, p_y1, nullptr, NTOK, TWOH, KEXP, nullptr);
    }
    // 5. KAN layer 2: expand + GEMM + 1.2*sigmoid(slope*·)
    {
        int total = NTOK * TWOH;
        expand_feat<<<(total + 255) / 256, 256>>>(p_y1, total);
        dim3 grid(NTOK / BMg, (IN_F + BNg - 1) / BNg);
        gemm_nt<2><<<grid, 256>>>(p_feat, p_Wp2, nullptr, out, nullptr, NTOK, IN_F, KEXP, slope);
    }
    (void)in_sizes; (void)n_in; (void)out_size;
}

// round 6
// speedup vs baseline: 2.0863x; 1.7206x over previous
#include <cuda_runtime.h>
#include <cuda_bf16.h>
#include <math.h>
#include <stdint.h>

// ---------------- problem constants ----------------
#define T_STEPS 600
#define BATCH   64
#define HID     40
#define IN_F    257
#define NTOK    (BATCH * T_STEPS)   // 38400
#define G3H     120                 // 3*HID
#define TWOH    80
#define KX_PAD  320                 // 257 padded to mult of 64
#define KF_PAD  768                 // 720 padded to mult of 64
#define N2_PAD  264                 // 257 padded to 3*88

// ---------------- scratch (static device memory; zero-initialized) ----------------
__device__ float g_giF[(size_t)T_STEPS * BATCH * G3H];
__device__ float g_giB[(size_t)T_STEPS * BATCH * G3H];
__device__ float g_hcat[(size_t)NTOK * TWOH];
__device__ float g_y1[(size_t)NTOK * TWOH];
__device__ __nv_bfloat16 g_xhi[(size_t)NTOK * KX_PAD];
__device__ __nv_bfloat16 g_xlo[(size_t)NTOK * KX_PAD];
__device__ __nv_bfloat16 g_fhi[(size_t)NTOK * KF_PAD];
__device__ __nv_bfloat16 g_flo[(size_t)NTOK * KF_PAD];
__device__ __nv_bfloat16 g_Wgh[2 * G3H * KX_PAD];
__device__ __nv_bfloat16 g_Wgl[2 * G3H * KX_PAD];
__device__ __nv_bfloat16 g_W1h[TWOH * KF_PAD];
__device__ __nv_bfloat16 g_W1l[TWOH * KF_PAD];
__device__ __nv_bfloat16 g_W2h[N2_PAD * KF_PAD];
__device__ __nv_bfloat16 g_W2l[N2_PAD * KF_PAD];

#define SMEM_SWIZZLE_128B(x) ((x) ^ (((x) >> 3) & 0x70))

__device__ __forceinline__ uint32_t smem_to_u32(const void* p) {
    uint32_t a;
    asm("{ .reg .u64 t; cvta.to.shared.u64 t, %1; cvt.u32.u64 %0, t; }" : "=r"(a) : "l"(p));
    return a;
}

// ---------------- warp MMA helpers (sm_80+ path, no tcgen05) ----------------
__device__ __forceinline__ void ldsm_x4(uint32_t* r, uint32_t addr) {
    asm volatile("ldmatrix.sync.aligned.m8n8.x4.shared.b16 {%0,%1,%2,%3}, [%4];"
                 : "=r"(r[0]), "=r"(r[1]), "=r"(r[2]), "=r"(r[3]) : "r"(addr));
}
__device__ __forceinline__ void ldsm_x2(uint32_t* r, uint32_t addr) {
    asm volatile("ldmatrix.sync.aligned.m8n8.x2.shared.b16 {%0,%1}, [%2];"
                 : "=r"(r[0]), "=r"(r[1]) : "r"(addr));
}
__device__ __forceinline__ void mma_bf16(float* c, const uint32_t* a, const uint32_t* b) {
    asm volatile("mma.sync.aligned.m16n8k16.row.col.f32.bf16.bf16.f32 "
                 "{%0,%1,%2,%3}, {%4,%5,%6,%7}, {%8,%9}, {%0,%1,%2,%3};"
                 : "+f"(c[0]), "+f"(c[1]), "+f"(c[2]), "+f"(c[3])
                 : "r"(a[0]), "r"(a[1]), "r"(a[2]), "r"(a[3]), "r"(b[0]), "r"(b[1]));
}

// ---------------- hi/lo split ----------------
__device__ __forceinline__ void split_bf16(float v, __nv_bfloat16& h, __nv_bfloat16& l) {
    h = __float2bfloat16(v);
    l = __float2bfloat16(v - __bfloat162float(h));
}

// ---------------- conversion kernels ----------------
__global__ void conv_x(const float* __restrict__ x) {
    int idx = blockIdx.x * blockDim.x + threadIdx.x;
    if (idx >= NTOK * KX_PAD) return;
    int row = idx / KX_PAD, col = idx % KX_PAD;
    float v = (col < IN_F) ? x[(size_t)row * IN_F + col] : 0.0f;
    __nv_bfloat16 h, l; split_bf16(v, h, l);
    g_xhi[idx] = h; g_xlo[idx] = l;
}

__global__ void pack_weights(const float* __restrict__ f0W, const float* __restrict__ b0W,
                             const float* __restrict__ k1b, const float* __restrict__ k1s,
                             const float* __restrict__ k1c,
                             const float* __restrict__ k2b, const float* __restrict__ k2s,
                             const float* __restrict__ k2c)
{
    const int NG = 2 * G3H * KX_PAD;       // 76800
    const int N1 = TWOH * KF_PAD;          // 61440
    const int N2 = N2_PAD * KF_PAD;        // 202752
    int idx = blockIdx.x * blockDim.x + threadIdx.x;
    if (idx >= NG + N1 + N2) return;
    float v = 0.0f;
    if (idx < NG) {
        int d = idx / (G3H * KX_PAD), r = (idx / KX_PAD) % G3H, c = idx % KX_PAD;
        if (c < IN_F) v = d ? b0W[r * IN_F + c] : f0W[r * IN_F + c];
        __nv_bfloat16 h, l; split_bf16(v, h, l);
        g_Wgh[idx] = h; g_Wgl[idx] = l;
        return;
    }
    idx -= NG;
    if (idx < N1) {
        int o = idx / KF_PAD, k = idx % KF_PAD;
        if (k < TWOH) v = k1b[o * TWOH + k];
        else if (k < 720) {
            int e = k - TWOH, i = e >> 3, g = e & 7;
            v = k1s[(o * TWOH + i) * 8 + g] * k1c[o * TWOH + i];
        }
        __nv_bfloat16 h, l; split_bf16(v, h, l);
        g_W1h[idx] = h; g_W1l[idx] = l;
        return;
    }
    idx -= N1;
    {
        int o = idx / KF_PAD, k = idx % KF_PAD;
        if (o < IN_F) {
            if (k < TWOH) v = k2b[o * TWOH + k];
            else if (k < 720) {
                int e = k - TWOH, i = e >> 3, g = e & 7;
                v = k2s[(o * TWOH + i) * 8 + g] * k2c[o * TWOH + i];
            }
        }
        __nv_bfloat16 h, l; split_bf16(v, h, l);
        g_W2h[idx] = h; g_W2l[idx] = l;
    }
}

// ---------------- KAN feature expansion -> bf16 hi/lo ----------------
__device__ __forceinline__ float gridv(int j) { return 0.4f * (float)(j - 3) - 1.0f; }

__global__ void expand_feat(const float* __restrict__ X, int total)
{
    int idx = blockIdx.x * blockDim.x + threadIdx.x;
    if (idx >= total) return;
    int n = idx / TWOH;
    int i = idx % TWOH;
    float x = X[idx];

    float su = x / (1.0f + expf(-x));
    {
        __nv_bfloat16 h, l; split_bf16(su, h, l);
        g_fhi[(size_t)n * KF_PAD + i] = h;
        g_flo[(size_t)n * KF_PAD + i] = l;
    }

    float bset[11];
#pragma unroll
    for (int j = 0; j < 11; j++)
        bset[j] = (x >= gridv(j) && x < gridv(j + 1)) ? 1.0f : 0.0f;
#pragma unroll
    for (int j = 0; j < 10; j++)
        bset[j] = (x - gridv(j)) * 2.5f * bset[j] + (gridv(j + 2) - x) * 2.5f * bset[j + 1];
#pragma unroll
    for (int j = 0; j < 9; j++)
        bset[j] = (x - gridv(j)) * 1.25f * bset[j] + (gridv(j + 3) - x) * 1.25f * bset[j + 1];
#pragma unroll
    for (int j = 0; j < 8; j++)
        bset[j] = (x - gridv(j)) * (1.0f / 1.2f) * bset[j] + (gridv(j + 4) - x) * (1.0f / 1.2f) * bset[j + 1];

    union { __nv_bfloat16 b[8]; uint4 u; } hv, lv;
#pragma unroll
    for (int j = 0; j < 8; j++) split_bf16(bset[j], hv.b[j], lv.b[j]);
    *(uint4*)&g_fhi[(size_t)n * KF_PAD + TWOH + i * 8] = hv.u;
    *(uint4*)&g_flo[(size_t)n * KF_PAD + TWOH + i * 8] = lv.u;
}

// ---------------- HMMA GEMM: D[64, N_TILE] = A[64,K] * B[N_TILE,K]^T ----------------
// hi/lo split: 3 MMA passes. EPI: 0=kan1 plain, 1=gates scatter+bias, 2=kan2 sigmoid
// 128 threads = 4 warps x 16 rows. K staged in 64-wide chunks, SW128-swizzled SMEM.
template <int N_TILE, int EPI>
__global__ __launch_bounds__(128) void hgemm(
    const __nv_bfloat16* __restrict__ Ahi, const __nv_bfloat16* __restrict__ Alo,
    const __nv_bfloat16* __restrict__ BhiAll, const __nv_bfloat16* __restrict__ BloAll,
    int K_pad,
    const float* __restrict__ biasF, const float* __restrict__ biasB,
    float* __restrict__ outF, float* __restrict__ outB,
    const float* __restrict__ slope)
{
    constexpr int NT8 = N_TILE / 8;

    __shared__ __align__(128) char sAhi[64 * 128];
    __shared__ __align__(128) char sAlo[64 * 128];
    __shared__ __align__(128) char sBhi[N_TILE * 128];
    __shared__ __align__(128) char sBlo[N_TILE * 128];

    const int tid = threadIdx.x;
    const int wid = tid >> 5;
    const int lid = tid & 31;

    const __nv_bfloat16* Bhi = BhiAll;
    const __nv_bfloat16* Blo = BloAll;
    if (EPI == 1) { Bhi += (size_t)blockIdx.y * G3H * K_pad; Blo += (size_t)blockIdx.y * G3H * K_pad; }
    if (EPI == 2) { Bhi += (size_t)blockIdx.y * 88 * K_pad;  Blo += (size_t)blockIdx.y * 88 * K_pad;  }

    const size_t aRow0 = (size_t)blockIdx.x * 64;

    const uint32_t aHiB = smem_to_u32(sAhi);
    const uint32_t aLoB = smem_to_u32(sAlo);
    const uint32_t bHiB = smem_to_u32(sBhi);
    const uint32_t bLoB = smem_to_u32(sBlo);

    float acc[NT8][4];
#pragma unroll
    for (int t = 0; t < NT8; t++)
#pragma unroll
        for (int j = 0; j < 4; j++) acc[t][j] = 0.0f;

    // ldmatrix lane roles
    const int rwA  = wid * 16 + (lid & 15);       // A row within CTA tile
    const int khA  = lid >> 4;                    // 0/1: k halves
    const int bTs  = (lid >> 4) & 1;              // B x4: tile select
    const int bKh  = (lid >> 3) & 1;              // B: k half
    const int bRow = lid & 7;                     // B: row within n8

    const int nchunk = K_pad >> 6;
    for (int kc = 0; kc < nchunk; kc++) {
        const int kOff = kc << 6;
        // load A chunk: 64 rows x 64 bf16 (128B rows), hi+lo
#pragma unroll
        for (int j = 0; j < 4; j++) {
            int s = j * 128 + tid;
            int r = s >> 3, c = s & 7;
            size_t gofs = (aRow0 + r) * (size_t)K_pad + kOff + c * 8;
            uint32_t sw = SMEM_SWIZZLE_128B((uint32_t)(r * 128 + c * 16));
            *(uint4*)(sAhi + sw) = *(const uint4*)(Ahi + gofs);
            *(uint4*)(sAlo + sw) = *(const uint4*)(Alo + gofs);
        }
        // load B chunk: N_TILE rows
        for (int s = tid; s < N_TILE * 8; s += 128) {
            int r = s >> 3, c = s & 7;
            size_t gofs = (size_t)r * K_pad + kOff + c * 8;
            uint32_t sw = SMEM_SWIZZLE_128B((uint32_t)(r * 128 + c * 16));
            *(uint4*)(sBhi + sw) = *(const uint4*)(Bhi + gofs);
            *(uint4*)(sBlo + sw) = *(const uint4*)(Blo + gofs);
        }
        __syncthreads();

#pragma unroll
        for (int ks = 0; ks < 4; ks++) {
            uint32_t ah[4], al[4];
            {
                uint32_t off = SMEM_SWIZZLE_128B((uint32_t)(rwA * 128 + ks * 32 + khA * 16));
                ldsm_x4(ah, aHiB + off);
                ldsm_x4(al, aLoB + off);
            }
#pragma unroll
            for (int nt = 0; nt < NT8; nt += 2) {
                uint32_t bh[4], bl[4];
                if (nt + 1 < NT8) {
                    int n = (nt + bTs) * 8 + bRow;
                    uint32_t off = SMEM_SWIZZLE_128B((uint32_t)(n * 128 + ks * 32 + bKh * 16));
                    ldsm_x4(bh, bHiB + off);
                    ldsm_x4(bl, bLoB + off);
                } else {
                    int n = nt * 8 + bRow;
                    uint32_t off = SMEM_SWIZZLE_128B((uint32_t)(n * 128 + ks * 32 + bKh * 16));
                    ldsm_x2(bh, bHiB + off);
                    ldsm_x2(bl, bLoB + off);
                }
                mma_bf16(acc[nt], ah, bh);
                mma_bf16(acc[nt], al, bh);
                mma_bf16(acc[nt], ah, bl);
                if (nt + 1 < NT8) {
                    mma_bf16(acc[nt + 1], ah, bh + 2);
                    mma_bf16(acc[nt + 1], al, bh + 2);
                    mma_bf16(acc[nt + 1], ah, bl + 2);
                }
            }
        }
        __syncthreads();
    }

    // epilogue: acc[t][0,1] -> row r0, cols cb,cb+1 ; acc[t][2,3] -> row r0+8
    const int r0 = (int)aRow0 + wid * 16 + (lid >> 2);
    const int cO = 2 * (lid & 3);
    if (EPI == 0) {
#pragma unroll
        for (int t = 0; t < NT8; t++) {
            int cb = t * 8 + cO;
            float* o0 = outF + (size_t)r0 * TWOH + cb;
            float* o1 = outF + (size_t)(r0 + 8) * TWOH + cb;
            o0[0] = acc[t][0]; o0[1] = acc[t][1];
            o1[0] = acc[t][2]; o1[1] = acc[t][3];
        }
    } else if (EPI == 1) {
        float* base = blockIdx.y ? outB : outF;
        const float* bia = blockIdx.y ? biasB : biasF;
        int b0 = r0 / T_STEPS, t0 = r0 % T_STEPS;
        int b1 = (r0 + 8) / T_STEPS, t1 = (r0 + 8) % T_STEPS;
        float* d0 = base + ((size_t)t0 * BATCH + b0) * G3H;
        float* d1 = base + ((size_t)t1 * BATCH + b1) * G3H;
#pragma unroll
        for (int t = 0; t < NT8; t++) {
            int cb = t * 8 + cO;
            d0[cb]     = acc[t][0] + bia[cb];
            d0[cb + 1] = acc[t][1] + bia[cb + 1];
            d1[cb]     = acc[t][2] + bia[cb];
            d1[cb + 1] = acc[t][3] + bia[cb + 1];
        }
    } else {
        const int cbase = blockIdx.y * 88;
#pragma unroll
        for (int t = 0; t < NT8; t++) {
            int cb = cbase + t * 8 + cO;
#pragma unroll
            for (int j = 0; j < 2; j++) {
                int cg = cb + j;
                if (cg < IN_F) {
                    outF[(size_t)r0 * IN_F + cg] =
                        1.2f / (1.0f + expf(-slope[cg] * acc[t][j]));
                    outF[(size_t)(r0 + 8) * IN_F + cg] =
                        1.2f / (1.0f + expf(-slope[cg] * acc[t][2 + j]));
                }
            }
        }
    }
}

// ---------------- GRU helpers ----------------
__device__ __forceinline__ float sigm_fast(float x) { return 1.0f / (1.0f + __expf(-x)); }
__device__ __forceinline__ float tanh_fast(float x) {
    float ax = fabsf(x);
    float e = __expf(-2.0f * ax);
    float t = (1.0f - e) / (1.0f + e);
    return copysignf(t, x);
}

// ---------------- GRU scan: 1 barrier/step, pipelined layers ----------------
__global__ __launch_bounds__(320) void gru_scan2(
    const float* __restrict__ WhhF0, const float* __restrict__ bhhF0,
    const float* __restrict__ WihF1, const float* __restrict__ WhhF1,
    const float* __restrict__ bihF1, const float* __restrict__ bhhF1,
    const float* __restrict__ WhhB0, const float* __restrict__ bhhB0,
    const float* __restrict__ WihB1, const float* __restrict__ WhhB1,
    const float* __restrict__ bihB1, const float* __restrict__ bhhB1)
{
    const int b   = blockIdx.x;
    const int dir = blockIdx.y;
    const float* Whh0 = dir ? WhhB0 : WhhF0;
    const float* bhh0 = dir ? bhhB0 : bhhF0;
    const float* W1ih = dir ? WihB1 : WihF1;
    const float* W1hh = dir ? WhhB1 : WhhF1;
    const float* b1ih = dir ? bihB1 : bihF1;
    const float* b1hh = dir ? bhhB1 : bhhF1;
    const float* gi   = dir ? g_giB : g_giF;
    float* out = g_hcat + (size_t)b * T_STEPS * TWOH + dir * HID;

    __shared__ float s_h0[2][HID];
    __shared__ float s_h1[2][HID];

    const int tid = threadIdx.x;
    const bool isA = tid < 160;
    const int lane = isA ? tid : tid - 160;
    const int unit = lane >> 2;
    const int q    = lane & 3;
    const int k0   = q * 10;

    float wA[3][10];
    float wI[3][10], wH[3][10];
    float brz0 = 0.f, brz1 = 0.f, bn0 = 0.f;
    float bR = 0.f, bZ = 0.f, bIN = 0.f, bHN = 0.f;
    if (isA) {
#pragma unroll
        for (int g = 0; g < 3; g++)
#pragma unroll
            for (int k = 0; k < 10; k++)
                wA[g][k] = Whh0[(g * HID + unit) * HID + k0 + k];
        brz0 = bhh0[unit];
        brz1 = bhh0[HID + unit];
        bn0  = bhh0[2 * HID + unit];
    } else {
#pragma unroll
        for (int g = 0; g < 3; g++)
#pragma unroll
            for (int k = 0; k < 10; k++) {
                wI[g][k] = W1ih[(g * HID + unit) * HID + k0 + k];
                wH[g][k] = W1hh[(g * HID + unit) * HID + k0 + k];
            }
        bR  = b1ih[unit]           + b1hh[unit];
        bZ  = b1ih[HID + unit]     + b1hh[HID + unit];
        bIN = b1ih[2 * HID + unit];
        bHN = b1hh[2 * HID + unit];
    }

    if (tid < HID) { s_h0[0][tid] = 0.0f; s_h0[1][tid] = 0.0f;
                     s_h1[0][tid] = 0.0f; s_h1[1][tid] = 0.0f; }

    float gc0 = 0.f, gc1 = 0.f, gc2 = 0.f;
    if (isA) {
        int grow = dir ? (T_STEPS - 1) : 0;
        const float* gp = gi + ((size_t)grow * BATCH + b) * G3H;
        gc0 = gp[unit]; gc1 = gp[HID + unit]; gc2 = gp[2 * HID + unit];
    }
    __syncthreads();

    for (int s = 0; s <= T_STEPS; s++) {
        const int cur = s & 1, nxt = (s & 1) ^ 1;
        float gn0 = 0.f, gn1 = 0.f, gn2 = 0.f;

        if (isA) {
            if (s + 1 < T_STEPS) {
                int grow = dir ? (T_STEPS - 2 - s) : (s + 1);
                const float* gp = gi + ((size_t)grow * BATCH + b) * G3H;
                gn0 = gp[unit]; gn1 = gp[HID + unit]; gn2 = gp[2 * HID + unit];
            }
            if (s < T_STEPS) {
                const float* h0c = s_h0[cur];
                float hk[10];
#pragma unroll
                for (int k = 0; k < 10; k++) hk[k] = h0c[k0 + k];
                float p0 = 0.f, p1 = 0.f, p2 = 0.f;
#pragma unroll
                for (int k = 0; k < 10; k++) {
                    p0 = fmaf(wA[0][k], hk[k], p0);
                    p1 = fmaf(wA[1][k], hk[k], p1);
                    p2 = fmaf(wA[2][k], hk[k], p2);
                }
                p0 += __shfl_xor_sync(0xffffffffu, p0, 1);
                p0 += __shfl_xor_sync(0xffffffffu, p0, 2);
                p1 += __shfl_xor_sync(0xffffffffu, p1, 1);
                p1 += __shfl_xor_sync(0xffffffffu, p1, 2);
                p2 += __shfl_xor_sync(0xffffffffu, p2, 1);
                p2 += __shfl_xor_sync(0xffffffffu, p2, 2);
                float r = sigm_fast(gc0 + p0 + brz0);
                float z = sigm_fast(gc1 + p1 + brz1);
                float n = tanh_fast(gc2 + r * (p2 + bn0));
                float hnew = (1.0f - z) * n + z * h0c[unit];
                if (q == 0) s_h0[nxt][unit] = hnew;
            }
        } else {
            if (s >= 1) {
                const float* h0c = s_h0[cur];
                const float* h1c = s_h1[cur];
                float a[10], hh[10];
#pragma unroll
                for (int k = 0; k < 10; k++) { a[k] = h0c[k0 + k]; hh[k] = h1c[k0 + k]; }
                float pr = 0.f, pz = 0.f, pin = 0.f, phn = 0.f;
#pragma unroll
                for (int k = 0; k < 10; k++) {
                    pr  = fmaf(wI[0][k], a[k], pr);
                    pz  = fmaf(wI[1][k], a[k], pz);
                    pin = fmaf(wI[2][k], a[k], pin);
                    phn = fmaf(wH[2][k], hh[k], phn);
                }
#pragma unroll
                for (int k = 0; k < 10; k++) {
                    pr = fmaf(wH[0][k], hh[k], pr);
                    pz = fmaf(wH[1][k], hh[k], pz);
                }
                pr  += __shfl_xor_sync(0xffffffffu, pr, 1);
                pr  += __shfl_xor_sync(0xffffffffu, pr, 2);
                pz  += __shfl_xor_sync(0xffffffffu, pz, 1);
                pz  += __shfl_xor_sync(0xffffffffu, pz, 2);
                pin += __shfl_xor_sync(0xffffffffu, pin, 1);
                pin += __shfl_xor_sync(0xffffffffu, pin, 2);
                phn += __shfl_xor_sync(0xffffffffu, phn, 1);
                phn += __shfl_xor_sync(0xffffffffu, phn, 2);
                float r = sigm_fast(pr + bR);
                float z = sigm_fast(pz + bZ);
                float n = tanh_fast(pin + bIN + r * (phn + bHN));
                float h = (1.0f - z) * n + z * h1c[unit];
                if (q == 0) {
                    s_h1[nxt][unit] = h;
                    out[(size_t)(s - 1) * TWOH + unit] = h;
                }
            }
        }
        __syncthreads();
        gc0 = gn0; gc1 = gn1; gc2 = gn2;
    }
}

// ---------------- launch ----------------
extern "C" void kernel_launch(void* const* d_in, const int* in_sizes, int n_in,
                              void* d_out, int out_size)
{
    const float* x     = (const float*)d_in[0];
    const float* f0Wih = (const float*)d_in[2];
    const float* f0Whh = (const float*)d_in[3];
    const float* f0bih = (const float*)d_in[4];
    const float* f0bhh = (const float*)d_in[5];
    const float* f1Wih = (const float*)d_in[6];
    const float* f1Whh = (const float*)d_in[7];
    const float* f1bih = (const float*)d_in[8];
    const float* f1bhh = (const float*)d_in[9];
    const float* b0Wih = (const float*)d_in[10];
    const float* b0Whh = (const float*)d_in[11];
    const float* b0bih = (const float*)d_in[12];
    const float* b0bhh = (const float*)d_in[13];
    const float* b1Wih = (const float*)d_in[14];
    const float* b1Whh = (const float*)d_in[15];
    const float* b1bih = (const float*)d_in[16];
    const float* b1bhh = (const float*)d_in[17];
    const float* k1b   = (const float*)d_in[18];
    const float* k1s   = (const float*)d_in[19];
    const float* k1c   = (const float*)d_in[20];
    const float* k2b   = (const float*)d_in[21];
    const float* k2s   = (const float*)d_in[22];
    const float* k2c   = (const float*)d_in[23];
    const float* slope = (const float*)d_in[24];
    float* out = (float*)d_out;

    float *p_giF, *p_giB, *p_hcat, *p_y1;
    __nv_bfloat16 *p_xhi, *p_xlo, *p_fhi, *p_flo, *p_Wgh, *p_Wgl, *p_W1h, *p_W1l, *p_W2h, *p_W2l;
    cudaGetSymbolAddress((void**)&p_giF, g_giF);
    cudaGetSymbolAddress((void**)&p_giB, g_giB);
    cudaGetSymbolAddress((void**)&p_hcat, g_hcat);
    cudaGetSymbolAddress((void**)&p_y1, g_y1);
    cudaGetSymbolAddress((void**)&p_xhi, g_xhi);
    cudaGetSymbolAddress((void**)&p_xlo, g_xlo);
    cudaGetSymbolAddress((void**)&p_fhi, g_fhi);
    cudaGetSymbolAddress((void**)&p_flo, g_flo);
    cudaGetSymbolAddress((void**)&p_Wgh, g_Wgh);
    cudaGetSymbolAddress((void**)&p_Wgl, g_Wgl);
    cudaGetSymbolAddress((void**)&p_W1h, g_W1h);
    cudaGetSymbolAddress((void**)&p_W1l, g_W1l);
    cudaGetSymbolAddress((void**)&p_W2h, g_W2h);
    cudaGetSymbolAddress((void**)&p_W2l, g_W2l);

    // 1. conversions
    conv_x<<<(NTOK * KX_PAD + 255) / 256, 256>>>(x);
    {
        int total = 2 * G3H * KX_PAD + TWOH * KF_PAD + N2_PAD * KF_PAD;
        pack_weights<<<(total + 255) / 256, 256>>>(f0Wih, b0Wih, k1b, k1s, k1c, k2b, k2s, k2c);
    }
    // 2. layer-0 input gates (both directions) via HMMA
    {
        dim3 grid(NTOK / 64, 2);
        hgemm<120, 1><<<grid, 128>>>(p_xhi, p_xlo, p_Wgh, p_Wgl, KX_PAD,
                                     f0bih, b0bih, p_giF, p_giB, nullptr);
    }
    // 3. bidirectional 2-layer GRU scan
    {
        dim3 grid(BATCH, 2);
        gru_scan2<<<grid, 320>>>(f0Whh, f0bhh, f1Wih, f1Whh, f1bih, f1bhh,
                                 b0Whh, b0bhh, b1Wih, b1Whh, b1bih, b1bhh);
    }
    // 4. KAN layer 1
    {
        expand_feat<<<(NTOK * TWOH + 255) / 256, 256>>>(p_hcat, NTOK * TWOH);
        dim3 grid(NTOK / 64, 1);
        hgemm<80, 0><<<grid, 128>>>(p_fhi, p_flo, p_W1h, p_W1l, KF_PAD,
                                    nullptr, nullptr, p_y1, nullptr, nullptr);
    }
    // 5. KAN layer 2 + final activation
    {
        expand_feat<<<(NTOK * TWOH + 255) / 256, 256>>>(p_y1, NTOK * TWOH);
        dim3 grid(NTOK / 64, 3);
        hgemm<88, 2><<<grid, 128>>>(p_fhi, p_flo, p_W2h, p_W2l, KF_PAD,
                                    nullptr, nullptr, out, nullptr, slope);
    }
    (void)in_sizes; (void)n_in; (void)out_size;
}

// round 7
// speedup vs baseline: 3.0693x; 1.4712x over previous
#include <cuda_runtime.h>
#include <cuda_bf16.h>
#include <math.h>
#include <stdint.h>

// ---------------- problem constants ----------------
#define T_STEPS 600
#define BATCH   64
#define HID     40
#define IN_F    257
#define NTOK    (BATCH * T_STEPS)   // 38400
#define G3H     120                 // 3*HID
#define TWOH    80
#define KX_PAD  320                 // 257 padded to mult of 64
#define KF_PAD  768                 // 720 padded to mult of 64
#define N2_PAD  264                 // 257 padded to 3*88

// ---------------- scratch (static device memory; zero-initialized) ----------------
__device__ float g_giF[(size_t)T_STEPS * BATCH * G3H];
__device__ float g_giB[(size_t)T_STEPS * BATCH * G3H];
__device__ float g_hcat[(size_t)NTOK * TWOH];
__device__ float g_y1[(size_t)NTOK * TWOH];
__device__ __nv_bfloat16 g_xhi[(size_t)NTOK * KX_PAD];
__device__ __nv_bfloat16 g_xlo[(size_t)NTOK * KX_PAD];
__device__ __nv_bfloat16 g_fhi[(size_t)NTOK * KF_PAD];
__device__ __nv_bfloat16 g_flo[(size_t)NTOK * KF_PAD];
__device__ __nv_bfloat16 g_Wgh[2 * G3H * KX_PAD];
__device__ __nv_bfloat16 g_Wgl[2 * G3H * KX_PAD];
__device__ __nv_bfloat16 g_W1h[TWOH * KF_PAD];
__device__ __nv_bfloat16 g_W1l[TWOH * KF_PAD];
__device__ __nv_bfloat16 g_W2h[N2_PAD * KF_PAD];
__device__ __nv_bfloat16 g_W2l[N2_PAD * KF_PAD];

#define SMEM_SWIZZLE_128B(x) ((x) ^ (((x) >> 3) & 0x70))

__device__ __forceinline__ uint32_t smem_to_u32(const void* p) {
    uint32_t a;
    asm("{ .reg .u64 t; cvta.to.shared.u64 t, %1; cvt.u32.u64 %0, t; }" : "=r"(a) : "l"(p));
    return a;
}

// ---------------- warp MMA helpers (sm_80+ path) ----------------
__device__ __forceinline__ void ldsm_x4(uint32_t* r, uint32_t addr) {
    asm volatile("ldmatrix.sync.aligned.m8n8.x4.shared.b16 {%0,%1,%2,%3}, [%4];"
                 : "=r"(r[0]), "=r"(r[1]), "=r"(r[2]), "=r"(r[3]) : "r"(addr));
}
__device__ __forceinline__ void ldsm_x2(uint32_t* r, uint32_t addr) {
    asm volatile("ldmatrix.sync.aligned.m8n8.x2.shared.b16 {%0,%1}, [%2];"
                 : "=r"(r[0]), "=r"(r[1]) : "r"(addr));
}
__device__ __forceinline__ void mma_bf16(float* c, const uint32_t* a, const uint32_t* b) {
    asm volatile("mma.sync.aligned.m16n8k16.row.col.f32.bf16.bf16.f32 "
                 "{%0,%1,%2,%3}, {%4,%5,%6,%7}, {%8,%9}, {%0,%1,%2,%3};"
                 : "+f"(c[0]), "+f"(c[1]), "+f"(c[2]), "+f"(c[3])
                 : "r"(a[0]), "r"(a[1]), "r"(a[2]), "r"(a[3]), "r"(b[0]), "r"(b[1]));
}

// ---------------- cp.async helpers ----------------
__device__ __forceinline__ void cp16(uint32_t saddr, const void* g) {
    asm volatile("cp.async.cg.shared.global [%0], [%1], 16;" :: "r"(saddr), "l"(g));
}
#define CP_COMMIT() asm volatile("cp.async.commit_group;" ::: "memory")
#define CP_WAIT1()  asm volatile("cp.async.wait_group 1;" ::: "memory")

// ---------------- hi/lo split ----------------
__device__ __forceinline__ void split_bf16(float v, __nv_bfloat16& h, __nv_bfloat16& l) {
    h = __float2bfloat16(v);
    l = __float2bfloat16(v - __bfloat162float(h));
}

// ---------------- conversion kernels ----------------
__global__ void conv_x(const float* __restrict__ x) {
    int idx = blockIdx.x * blockDim.x + threadIdx.x;
    if (idx >= NTOK * KX_PAD) return;
    int row = idx / KX_PAD, col = idx % KX_PAD;
    float v = (col < IN_F) ? x[(size_t)row * IN_F + col] : 0.0f;
    __nv_bfloat16 h, l; split_bf16(v, h, l);
    g_xhi[idx] = h; g_xlo[idx] = l;
}

__global__ void pack_weights(const float* __restrict__ f0W, const float* __restrict__ b0W,
                             const float* __restrict__ k1b, const float* __restrict__ k1s,
                             const float* __restrict__ k1c,
                             const float* __restrict__ k2b, const float* __restrict__ k2s,
                             const float* __restrict__ k2c)
{
    const int NG = 2 * G3H * KX_PAD;
    const int N1 = TWOH * KF_PAD;
    const int N2 = N2_PAD * KF_PAD;
    int idx = blockIdx.x * blockDim.x + threadIdx.x;
    if (idx >= NG + N1 + N2) return;
    float v = 0.0f;
    if (idx < NG) {
        int d = idx / (G3H * KX_PAD), r = (idx / KX_PAD) % G3H, c = idx % KX_PAD;
        if (c < IN_F) v = d ? b0W[r * IN_F + c] : f0W[r * IN_F + c];
        __nv_bfloat16 h, l; split_bf16(v, h, l);
        g_Wgh[idx] = h; g_Wgl[idx] = l;
        return;
    }
    idx -= NG;
    if (idx < N1) {
        int o = idx / KF_PAD, k = idx % KF_PAD;
        if (k < TWOH) v = k1b[o * TWOH + k];
        else if (k < 720) {
            int e = k - TWOH, i = e >> 3, g = e & 7;
            v = k1s[(o * TWOH + i) * 8 + g] * k1c[o * TWOH + i];
        }
        __nv_bfloat16 h, l; split_bf16(v, h, l);
        g_W1h[idx] = h; g_W1l[idx] = l;
        return;
    }
    idx -= N1;
    {
        int o = idx / KF_PAD, k = idx % KF_PAD;
        if (o < IN_F) {
            if (k < TWOH) v = k2b[o * TWOH + k];
            else if (k < 720) {
                int e = k - TWOH, i = e >> 3, g = e & 7;
                v = k2s[(o * TWOH + i) * 8 + g] * k2c[o * TWOH + i];
            }
        }
        __nv_bfloat16 h, l; split_bf16(v, h, l);
        g_W2h[idx] = h; g_W2l[idx] = l;
    }
}

// ---------------- KAN feature expansion -> bf16 hi/lo ----------------
__device__ __forceinline__ float gridv(int j) { return 0.4f * (float)(j - 3) - 1.0f; }

__global__ void expand_feat(const float* __restrict__ X, int total)
{
    int idx = blockIdx.x * blockDim.x + threadIdx.x;
    if (idx >= total) return;
    int n = idx / TWOH;
    int i = idx % TWOH;
    float x = X[idx];

    float su = x / (1.0f + expf(-x));
    {
        __nv_bfloat16 h, l; split_bf16(su, h, l);
        g_fhi[(size_t)n * KF_PAD + i] = h;
        g_flo[(size_t)n * KF_PAD + i] = l;
    }

    float bset[11];
#pragma unroll
    for (int j = 0; j < 11; j++)
        bset[j] = (x >= gridv(j) && x < gridv(j + 1)) ? 1.0f : 0.0f;
#pragma unroll
    for (int j = 0; j < 10; j++)
        bset[j] = (x - gridv(j)) * 2.5f * bset[j] + (gridv(j + 2) - x) * 2.5f * bset[j + 1];
#pragma unroll
    for (int j = 0; j < 9; j++)
        bset[j] = (x - gridv(j)) * 1.25f * bset[j] + (gridv(j + 3) - x) * 1.25f * bset[j + 1];
#pragma unroll
    for (int j = 0; j < 8; j++)
        bset[j] = (x - gridv(j)) * (1.0f / 1.2f) * bset[j] + (gridv(j + 4) - x) * (1.0f / 1.2f) * bset[j + 1];

    union { __nv_bfloat16 b[8]; uint4 u; } hv, lv;
#pragma unroll
    for (int j = 0; j < 8; j++) split_bf16(bset[j], hv.b[j], lv.b[j]);
    *(uint4*)&g_fhi[(size_t)n * KF_PAD + TWOH + i * 8] = hv.u;
    *(uint4*)&g_flo[(size_t)n * KF_PAD + TWOH + i * 8] = lv.u;
}

// ---------------- HMMA GEMM with cp.async 2-stage pipeline ----------------
// D[64, N_TILE] = A[64,K] * B[N_TILE,K]^T, hi/lo 3-pass.
// EPI: 0=kan1 plain, 1=gates scatter+bias, 2=kan2 sigmoid
template <int N_TILE>
struct TG {
    static constexpr int N128    = N_TILE * 128;
    static constexpr int OFF_AHI = 0;
    static constexpr int OFF_ALO = 8192;
    static constexpr int OFF_BHI = 16384;
    static constexpr int OFF_BLO = 16384 + N128;
    static constexpr int STAGE   = 16384 + 2 * N128;
    static constexpr int TOTAL   = 2 * STAGE;
};

template <int N_TILE, int EPI>
__global__ __launch_bounds__(128) void hgemm(
    const __nv_bfloat16* __restrict__ Ahi, const __nv_bfloat16* __restrict__ Alo,
    const __nv_bfloat16* __restrict__ BhiAll, const __nv_bfloat16* __restrict__ BloAll,
    int K_pad,
    const float* __restrict__ biasF, const float* __restrict__ biasB,
    float* __restrict__ outF, float* __restrict__ outB,
    const float* __restrict__ slope)
{
    constexpr int NT8 = N_TILE / 8;
    extern __shared__ __align__(128) char smem[];
    const uint32_t smemB = smem_to_u32(smem);

    const int tid = threadIdx.x;
    const int wid = tid >> 5;
    const int lid = tid & 31;

    const __nv_bfloat16* Bhi = BhiAll;
    const __nv_bfloat16* Blo = BloAll;
    if (EPI == 1) { Bhi += (size_t)blockIdx.y * G3H * K_pad; Blo += (size_t)blockIdx.y * G3H * K_pad; }
    if (EPI == 2) { Bhi += (size_t)blockIdx.y * 88 * K_pad;  Blo += (size_t)blockIdx.y * 88 * K_pad;  }

    const size_t aRow0 = (size_t)blockIdx.x * 64;

    float acc[NT8][4];
#pragma unroll
    for (int t = 0; t < NT8; t++)
#pragma unroll
        for (int j = 0; j < 4; j++) acc[t][j] = 0.0f;

    // ldmatrix lane roles
    const int rwA  = wid * 16 + (lid & 15);
    const int khA  = lid >> 4;
    const int bTs  = (lid >> 4) & 1;
    const int bKh  = (lid >> 3) & 1;
    const int bRow = lid & 7;

    auto load_chunk = [&](int kc, int st) {
        const int kOff = kc << 6;
        const uint32_t base = smemB + st * TG<N_TILE>::STAGE;
#pragma unroll
        for (int j = 0; j < 4; j++) {
            int s = j * 128 + tid;
            int r = s >> 3, c = s & 7;
            size_t gofs = (aRow0 + r) * (size_t)K_pad + kOff + c * 8;
            uint32_t sw = SMEM_SWIZZLE_128B((uint32_t)(r * 128 + c * 16));
            cp16(base + TG<N_TILE>::OFF_AHI + sw, Ahi + gofs);
            cp16(base + TG<N_TILE>::OFF_ALO + sw, Alo + gofs);
        }
        for (int s = tid; s < N_TILE * 8; s += 128) {
            int r = s >> 3, c = s & 7;
            size_t gofs = (size_t)r * K_pad + kOff + c * 8;
            uint32_t sw = SMEM_SWIZZLE_128B((uint32_t)(r * 128 + c * 16));
            cp16(base + TG<N_TILE>::OFF_BHI + sw, Bhi + gofs);
            cp16(base + TG<N_TILE>::OFF_BLO + sw, Blo + gofs);
        }
    };

    const int nchunk = K_pad >> 6;
    load_chunk(0, 0);
    CP_COMMIT();

    for (int kc = 0; kc < nchunk; kc++) {
        if (kc + 1 < nchunk) load_chunk(kc + 1, (kc + 1) & 1);
        CP_COMMIT();
        CP_WAIT1();
        __syncthreads();

        const uint32_t base = smemB + (kc & 1) * TG<N_TILE>::STAGE;
        const uint32_t aHiB = base + TG<N_TILE>::OFF_AHI;
        const uint32_t aLoB = base + TG<N_TILE>::OFF_ALO;
        const uint32_t bHiB = base + TG<N_TILE>::OFF_BHI;
        const uint32_t bLoB = base + TG<N_TILE>::OFF_BLO;

#pragma unroll
        for (int ks = 0; ks < 4; ks++) {
            uint32_t ah[4], al[4];
            {
                uint32_t off = SMEM_SWIZZLE_128B((uint32_t)(rwA * 128 + ks * 32 + khA * 16));
                ldsm_x4(ah, aHiB + off);
                ldsm_x4(al, aLoB + off);
            }
#pragma unroll
            for (int nt = 0; nt < NT8; nt += 2) {
                uint32_t bh[4], bl[4];
                if (nt + 1 < NT8) {
                    int n = (nt + bTs) * 8 + bRow;
                    uint32_t off = SMEM_SWIZZLE_128B((uint32_t)(n * 128 + ks * 32 + bKh * 16));
                    ldsm_x4(bh, bHiB + off);
                    ldsm_x4(bl, bLoB + off);
                } else {
                    int n = nt * 8 + bRow;
                    uint32_t off = SMEM_SWIZZLE_128B((uint32_t)(n * 128 + ks * 32 + bKh * 16));
                    ldsm_x2(bh, bHiB + off);
                    ldsm_x2(bl, bLoB + off);
                }
                mma_bf16(acc[nt], ah, bh);
                mma_bf16(acc[nt], al, bh);
                mma_bf16(acc[nt], ah, bl);
                if (nt + 1 < NT8) {
                    mma_bf16(acc[nt + 1], ah, bh + 2);
                    mma_bf16(acc[nt + 1], al, bh + 2);
                    mma_bf16(acc[nt + 1], ah, bl + 2);
                }
            }
        }
        __syncthreads();
    }

    // epilogue
    const int r0 = (int)aRow0 + wid * 16 + (lid >> 2);
    const int cO = 2 * (lid & 3);
    if (EPI == 0) {
#pragma unroll
        for (int t = 0; t < NT8; t++) {
            int cb = t * 8 + cO;
            float* o0 = outF + (size_t)r0 * TWOH + cb;
            float* o1 = outF + (size_t)(r0 + 8) * TWOH + cb;
            o0[0] = acc[t][0]; o0[1] = acc[t][1];
            o1[0] = acc[t][2]; o1[1] = acc[t][3];
        }
    } else if (EPI == 1) {
        float* base = blockIdx.y ? outB : outF;
        const float* bia = blockIdx.y ? biasB : biasF;
        int b0 = r0 / T_STEPS, t0 = r0 % T_STEPS;
        int b1 = (r0 + 8) / T_STEPS, t1 = (r0 + 8) % T_STEPS;
        float* d0 = base + ((size_t)t0 * BATCH + b0) * G3H;
        float* d1 = base + ((size_t)t1 * BATCH + b1) * G3H;
#pragma unroll
        for (int t = 0; t < NT8; t++) {
            int cb = t * 8 + cO;
            d0[cb]     = acc[t][0] + bia[cb];
            d0[cb + 1] = acc[t][1] + bia[cb + 1];
            d1[cb]     = acc[t][2] + bia[cb];
            d1[cb + 1] = acc[t][3] + bia[cb + 1];
        }
    } else {
        const int cbase = blockIdx.y * 88;
#pragma unroll
        for (int t = 0; t < NT8; t++) {
            int cb = cbase + t * 8 + cO;
#pragma unroll
            for (int j = 0; j < 2; j++) {
                int cg = cb + j;
                if (cg < IN_F) {
                    outF[(size_t)r0 * IN_F + cg] =
                        1.2f / (1.0f + expf(-slope[cg] * acc[t][j]));
                    outF[(size_t)(r0 + 8) * IN_F + cg] =
                        1.2f / (1.0f + expf(-slope[cg] * acc[t][2 + j]));
                }
            }
        }
    }
}

// ---------------- GRU helpers: no IEEE div on the chain ----------------
__device__ __forceinline__ float sigm_fast(float x) {
    float e = __expf(-x);
    return __fdividef(1.0f, 1.0f + e);
}
__device__ __forceinline__ float tanh_fast(float x) {
    float e = __expf(2.0f * x);                 // inf for large x is fine
    return 1.0f - __fdividef(2.0f, 1.0f + e);   // x->-inf: 1-2=-1; x->+inf: 1-0=1
}

// ---------------- GRU scan: 1 barrier/step, pipelined layers ----------------
__global__ __launch_bounds__(320) void gru_scan2(
    const float* __restrict__ WhhF0, const float* __restrict__ bhhF0,
    const float* __restrict__ WihF1, const float* __restrict__ WhhF1,
    const float* __restrict__ bihF1, const float* __restrict__ bhhF1,
    const float* __restrict__ WhhB0, const float* __restrict__ bhhB0,
    const float* __restrict__ WihB1, const float* __restrict__ WhhB1,
    const float* __restrict__ bihB1, const float* __restrict__ bhhB1)
{
    const int b   = blockIdx.x;
    const int dir = blockIdx.y;
    const float* Whh0 = dir ? WhhB0 : WhhF0;
    const float* bhh0 = dir ? bhhB0 : bhhF0;
    const float* W1ih = dir ? WihB1 : WihF1;
    const float* W1hh = dir ? WhhB1 : WhhF1;
    const float* b1ih = dir ? bihB1 : bihF1;
    const float* b1hh = dir ? bhhB1 : bhhF1;
    const float* gi   = dir ? g_giB : g_giF;
    float* out = g_hcat + (size_t)b * T_STEPS * TWOH + dir * HID;

    __shared__ float s_h0[2][HID];
    __shared__ float s_h1[2][HID];

    const int tid = threadIdx.x;
    const bool isA = tid < 160;
    const int lane = isA ? tid : tid - 160;
    const int unit = lane >> 2;
    const int q    = lane & 3;
    const int k0   = q * 10;

    float wA[3][10];
    float wI[3][10], wH[3][10];
    float brz0 = 0.f, brz1 = 0.f, bn0 = 0.f;
    float bR = 0.f, bZ = 0.f, bIN = 0.f, bHN = 0.f;
    if (isA) {
#pragma unroll
        for (int g = 0; g < 3; g++)
#pragma unroll
            for (int k = 0; k < 10; k++)
                wA[g][k] = Whh0[(g * HID + unit) * HID + k0 + k];
        brz0 = bhh0[unit];
        brz1 = bhh0[HID + unit];
        bn0  = bhh0[2 * HID + unit];
    } else {
#pragma unroll
        for (int g = 0; g < 3; g++)
#pragma unroll
            for (int k = 0; k < 10; k++) {
                wI[g][k] = W1ih[(g * HID + unit) * HID + k0 + k];
                wH[g][k] = W1hh[(g * HID + unit) * HID + k0 + k];
            }
        bR  = b1ih[unit]           + b1hh[unit];
        bZ  = b1ih[HID + unit]     + b1hh[HID + unit];
        bIN = b1ih[2 * HID + unit];
        bHN = b1hh[2 * HID + unit];
    }

    if (tid < HID) { s_h0[0][tid] = 0.0f; s_h0[1][tid] = 0.0f;
                     s_h1[0][tid] = 0.0f; s_h1[1][tid] = 0.0f; }

    float gc0 = 0.f, gc1 = 0.f, gc2 = 0.f;
    if (isA) {
        int grow = dir ? (T_STEPS - 1) : 0;
        const float* gp = gi + ((size_t)grow * BATCH + b) * G3H;
        gc0 = gp[unit]; gc1 = gp[HID + unit]; gc2 = gp[2 * HID + unit];
    }
    __syncthreads();

    for (int s = 0; s <= T_STEPS; s++) {
        const int cur = s & 1, nxt = (s & 1) ^ 1;
        float gn0 = 0.f, gn1 = 0.f, gn2 = 0.f;

        if (isA) {
            if (s + 1 < T_STEPS) {
                int grow = dir ? (T_STEPS - 2 - s) : (s + 1);
                const float* gp = gi + ((size_t)grow * BATCH + b) * G3H;
                gn0 = gp[unit]; gn1 = gp[HID + unit]; gn2 = gp[2 * HID + unit];
            }
            if (s < T_STEPS) {
                const float* h0c = s_h0[cur];
                float hk[10];
#pragma unroll
                for (int k = 0; k < 10; k++) hk[k] = h0c[k0 + k];
                float p0 = 0.f, p1 = 0.f, p2 = 0.f;
#pragma unroll
                for (int k = 0; k < 10; k++) {
                    p0 = fmaf(wA[0][k], hk[k], p0);
                    p1 = fmaf(wA[1][k], hk[k], p1);
                    p2 = fmaf(wA[2][k], hk[k], p2);
                }
                p0 += __shfl_xor_sync(0xffffffffu, p0, 1);
                p0 += __shfl_xor_sync(0xffffffffu, p0, 2);
                p1 += __shfl_xor_sync(0xffffffffu, p1, 1);
                p1 += __shfl_xor_sync(0xffffffffu, p1, 2);
                p2 += __shfl_xor_sync(0xffffffffu, p2, 1);
                p2 += __shfl_xor_sync(0xffffffffu, p2, 2);
                float r = sigm_fast(gc0 + p0 + brz0);
                float z = sigm_fast(gc1 + p1 + brz1);
                float n = tanh_fast(gc2 + r * (p2 + bn0));
                float hnew = (1.0f - z) * n + z * h0c[unit];
                if (q == 0) s_h0[nxt][unit] = hnew;
            }
        } else {
            if (s >= 1) {
                const float* h0c = s_h0[cur];
                const float* h1c = s_h1[cur];
                float a[10], hh[10];
#pragma unroll
                for (int k = 0; k < 10; k++) { a[k] = h0c[k0 + k]; hh[k] = h1c[k0 + k]; }
                float pr = 0.f, pz = 0.f, pin = 0.f, phn = 0.f;
#pragma unroll
                for (int k = 0; k < 10; k++) {
                    pr  = fmaf(wI[0][k], a[k], pr);
                    pz  = fmaf(wI[1][k], a[k], pz);
                    pin = fmaf(wI[2][k], a[k], pin);
                    phn = fmaf(wH[2][k], hh[k], phn);
                }
#pragma unroll
                for (int k = 0; k < 10; k++) {
                    pr = fmaf(wH[0][k], hh[k], pr);
                    pz = fmaf(wH[1][k], hh[k], pz);
                }
                pr  += __shfl_xor_sync(0xffffffffu, pr, 1);
                pr  += __shfl_xor_sync(0xffffffffu, pr, 2);
                pz  += __shfl_xor_sync(0xffffffffu, pz, 1);
                pz  += __shfl_xor_sync(0xffffffffu, pz, 2);
                pin += __shfl_xor_sync(0xffffffffu, pin, 1);
                pin += __shfl_xor_sync(0xffffffffu, pin, 2);
                phn += __shfl_xor_sync(0xffffffffu, phn, 1);
                phn += __shfl_xor_sync(0xffffffffu, phn, 2);
                float r = sigm_fast(pr + bR);
                float z = sigm_fast(pz + bZ);
                float n = tanh_fast(pin + bIN + r * (phn + bHN));
                float h = (1.0f - z) * n + z * h1c[unit];
                if (q == 0) {
                    s_h1[nxt][unit] = h;
                    out[(size_t)(s - 1) * TWOH + unit] = h;
                }
            }
        }
        __syncthreads();
        gc0 = gn0; gc1 = gn1; gc2 = gn2;
    }
}

// ---------------- launch ----------------
extern "C" void kernel_launch(void* const* d_in, const int* in_sizes, int n_in,
                              void* d_out, int out_size)
{
    const float* x     = (const float*)d_in[0];
    const float* f0Wih = (const float*)d_in[2];
    const float* f0Whh = (const float*)d_in[3];
    const float* f0bih = (const float*)d_in[4];
    const float* f0bhh = (const float*)d_in[5];
    const float* f1Wih = (const float*)d_in[6];
    const float* f1Whh = (const float*)d_in[7];
    const float* f1bih = (const float*)d_in[8];
    const float* f1bhh = (const float*)d_in[9];
    const float* b0Wih = (const float*)d_in[10];
    const float* b0Whh = (const float*)d_in[11];
    const float* b0bih = (const float*)d_in[12];
    const float* b0bhh = (const float*)d_in[13];
    const float* b1Wih = (const float*)d_in[14];
    const float* b1Whh = (const float*)d_in[15];
    const float* b1bih = (const float*)d_in[16];
    const float* b1bhh = (const float*)d_in[17];
    const float* k1b   = (const float*)d_in[18];
    const float* k1s   = (const float*)d_in[19];
    const float* k1c   = (const float*)d_in[20];
    const float* k2b   = (const float*)d_in[21];
    const float* k2s   = (const float*)d_in[22];
    const float* k2c   = (const float*)d_in[23];
    const float* slope = (const float*)d_in[24];
    float* out = (float*)d_out;

    float *p_giF, *p_giB, *p_hcat, *p_y1;
    __nv_bfloat16 *p_xhi, *p_xlo, *p_fhi, *p_flo, *p_Wgh, *p_Wgl, *p_W1h, *p_W1l, *p_W2h, *p_W2l;
    cudaGetSymbolAddress((void**)&p_giF, g_giF);
    cudaGetSymbolAddress((void**)&p_giB, g_giB);
    cudaGetSymbolAddress((void**)&p_hcat, g_hcat);
    cudaGetSymbolAddress((void**)&p_y1, g_y1);
    cudaGetSymbolAddress((void**)&p_xhi, g_xhi);
    cudaGetSymbolAddress((void**)&p_xlo, g_xlo);
    cudaGetSymbolAddress((void**)&p_fhi, g_fhi);
    cudaGetSymbolAddress((void**)&p_flo, g_flo);
    cudaGetSymbolAddress((void**)&p_Wgh, g_Wgh);
    cudaGetSymbolAddress((void**)&p_Wgl, g_Wgl);
    cudaGetSymbolAddress((void**)&p_W1h, g_W1h);
    cudaGetSymbolAddress((void**)&p_W1l, g_W1l);
    cudaGetSymbolAddress((void**)&p_W2h, g_W2h);
    cudaGetSymbolAddress((void**)&p_W2l, g_W2l);

    // idempotent; safe to call on every launch (not a stream op, not captured)
    cudaFuncSetAttribute(hgemm<120, 1>, cudaFuncAttributeMaxDynamicSharedMemorySize, TG<120>::TOTAL);
    cudaFuncSetAttribute(hgemm<80, 0>,  cudaFuncAttributeMaxDynamicSharedMemorySize, TG<80>::TOTAL);
    cudaFuncSetAttribute(hgemm<88, 2>,  cudaFuncAttributeMaxDynamicSharedMemorySize, TG<88>::TOTAL);

    // 1. conversions
    conv_x<<<(NTOK * KX_PAD + 255) / 256, 256>>>(x);
    {
        int total = 2 * G3H * KX_PAD + TWOH * KF_PAD + N2_PAD * KF_PAD;
        pack_weights<<<(total + 255) / 256, 256>>>(f0Wih, b0Wih, k1b, k1s, k1c, k2b, k2s, k2c);
    }
    // 2. layer-0 input gates (both directions) via HMMA
    {
        dim3 grid(NTOK / 64, 2);
        hgemm<120, 1><<<grid, 128, TG<120>::TOTAL>>>(p_xhi, p_xlo, p_Wgh, p_Wgl, KX_PAD,
                                                     f0bih, b0bih, p_giF, p_giB, nullptr);
    }
    // 3. bidirectional 2-layer GRU scan
    {
        dim3 grid(BATCH, 2);
        gru_scan2<<<grid, 320>>>(f0Whh, f0bhh, f1Wih, f1Whh, f1bih, f1bhh,
                                 b0Whh, b0bhh, b1Wih, b1Whh, b1bih, b1bhh);
    }
    // 4. KAN layer 1
    {
        expand_feat<<<(NTOK * TWOH + 255) / 256, 256>>>(p_hcat, NTOK * TWOH);
        dim3 grid(NTOK / 64, 1);
        hgemm<80, 0><<<grid, 128, TG<80>::TOTAL>>>(p_fhi, p_flo, p_W1h, p_W1l, KF_PAD,
                                                   nullptr, nullptr, p_y1, nullptr, nullptr);
    }
    // 5. KAN layer 2 + final activation
    {
        expand_feat<<<(NTOK * TWOH + 255) / 256, 256>>>(p_y1, NTOK * TWOH);
        dim3 grid(NTOK / 64, 3);
        hgemm<88, 2><<<grid, 128, TG<88>::TOTAL>>>(p_fhi, p_flo, p_W2h, p_W2l, KF_PAD,
                                                   nullptr, nullptr, out, nullptr, slope);
    }
    (void)in_sizes; (void)n_in; (void)out_size;
}